// round 5
// baseline (speedup 1.0000x reference)
#include <cuda_runtime.h>
#include <cstdint>

// ---------------- problem constants (fixed by this input set) ----------------
#define BATCH    8
#define NPTS     8192
#define NTOT     65536
#define NPOINT   512
#define NSAMPLE  32
#define CIN      64
#define R2       (0.1f * 0.1f)

// d_out packing (float32), tuple flattened in return order:
#define OFF_XYZ   0                                   // new_xyz  [8,512,3]
#define OFF_IDX   (BATCH * NPOINT * 3)                // new_idx  [8,512]
#define OFF_FEAT  (OFF_IDX + BATCH * NPOINT)          // new_feat [8,128,512]
#define OFF_SIDS  (OFF_FEAT + BATCH * 128 * NPOINT)   // sample_ids [8,512,32]

// ---------------- scratch (device globals; no runtime allocation) ------------
__device__ int   g_new_idx[BATCH * NPOINT];
__device__ float g_new_xyz[BATCH * NPOINT * 3];
__device__ int   g_sample_ids[BATCH * NPOINT * NSAMPLE];
__device__ float g_featT[(size_t)NTOT * CIN];   // [n][c] transposed features

// ---------------- packed f32x2 helpers (bit-exact per-lane fp32) -------------
__device__ __forceinline__ unsigned long long f2_add(unsigned long long a, unsigned long long b) {
    unsigned long long r;
    asm("add.rn.f32x2 %0, %1, %2;" : "=l"(r) : "l"(a), "l"(b));
    return r;
}
__device__ __forceinline__ unsigned long long f2_mul(unsigned long long a, unsigned long long b) {
    unsigned long long r;
    asm("mul.rn.f32x2 %0, %1, %2;" : "=l"(r) : "l"(a), "l"(b));
    return r;
}
__device__ __forceinline__ unsigned long long f2_pack(float lo, float hi) {
    unsigned long long r;
    asm("mov.b64 %0, {%1, %2};" : "=l"(r) : "f"(lo), "f"(hi));
    return r;
}
__device__ __forceinline__ void f2_unpack(unsigned long long v, float& lo, float& hi) {
    asm("mov.b64 {%0, %1}, %2;" : "=f"(lo), "=f"(hi) : "l"(v));
}

extern __shared__ float dyn_smem[];

// =============================================================================
// 1) Furthest point sampling: 1 block per batch, 512 threads, 16 pts/thread.
//    Packed f32x2 distances (bit-exact (dx^2+dy^2)+dz^2), deferred argmax,
//    32-bit value shuffle reduce + ballot index resolution, 1 barrier/iter.
// =============================================================================
__global__ void __launch_bounds__(512) fps_kernel(const float* __restrict__ xyz,
                                                  float* __restrict__ out) {
    float* spx = dyn_smem;
    float* spy = spx + NPTS;
    float* spz = spy + NPTS;
    __shared__ float red_val[2][16];
    __shared__ int   red_idx[2][16];

    const int b = blockIdx.x;
    const int t = threadIdx.x;
    const float* src = xyz + (size_t)b * NPTS * 3;

    // load 16 consecutive points (48 floats = 12 float4)
    float f[48];
    {
        const float4* s4 = (const float4*)src;
        float4* f4 = (float4*)f;
#pragma unroll
        for (int i = 0; i < 12; i++) f4[i] = s4[t * 12 + i];
    }
    unsigned long long pxp[8], pyp[8], pzp[8];
    float dd[16];
#pragma unroll
    for (int a = 0; a < 8; a++) {
        pxp[a] = f2_pack(f[6 * a + 0], f[6 * a + 3]);
        pyp[a] = f2_pack(f[6 * a + 1], f[6 * a + 4]);
        pzp[a] = f2_pack(f[6 * a + 2], f[6 * a + 5]);
    }
#pragma unroll
    for (int j = 0; j < 16; j++) {
        dd[j] = 1e10f;
        spx[t * 16 + j] = f[3 * j + 0];
        spy[t * 16 + j] = f[3 * j + 1];
        spz[t * 16 + j] = f[3 * j + 2];
    }
    if (t == 0) {
        g_new_idx[b * NPOINT] = 0;
        g_new_xyz[(size_t)(b * NPOINT) * 3 + 0] = f[0];
        g_new_xyz[(size_t)(b * NPOINT) * 3 + 1] = f[1];
        g_new_xyz[(size_t)(b * NPOINT) * 3 + 2] = f[2];
        out[OFF_IDX + b * NPOINT] = 0.0f;
        out[OFF_XYZ + (size_t)(b * NPOINT) * 3 + 0] = f[0];
        out[OFF_XYZ + (size_t)(b * NPOINT) * 3 + 1] = f[1];
        out[OFF_XYZ + (size_t)(b * NPOINT) * 3 + 2] = f[2];
    }
    __syncthreads();

    // negated last-point coords, packed (x - l == x + (-l), exact)
    float lx0 = spx[0], ly0 = spy[0], lz0 = spz[0];
    unsigned long long nlx = f2_pack(-lx0, -lx0);
    unsigned long long nly = f2_pack(-ly0, -ly0);
    unsigned long long nlz = f2_pack(-lz0, -lz0);

    const int lane = t & 31, wid = t >> 5;

    for (int it = 1; it < NPOINT; ++it) {
        float m = -1.0f;
#pragma unroll
        for (int a = 0; a < 8; a++) {
            unsigned long long dx = f2_add(pxp[a], nlx);
            unsigned long long dy = f2_add(pyp[a], nly);
            unsigned long long dz = f2_add(pzp[a], nlz);
            unsigned long long s  = f2_add(f2_add(f2_mul(dx, dx), f2_mul(dy, dy)),
                                           f2_mul(dz, dz));
            float d2l, d2h;
            f2_unpack(s, d2l, d2h);
            float n0 = fminf(dd[2 * a + 0], d2l);
            float n1 = fminf(dd[2 * a + 1], d2h);
            dd[2 * a + 0] = n0;
            dd[2 * a + 1] = n1;
            m = fmaxf(m, n0);
            m = fmaxf(m, n1);
        }
        // deferred argmax: lowest j matching m (reverse scan)
        int mi = 0;
#pragma unroll
        for (int j = 15; j >= 0; --j)
            if (dd[j] == m) mi = j;

        // warp value-only max reduce (32-bit)
        float wm = m;
#pragma unroll
        for (int off = 16; off; off >>= 1)
            wm = fmaxf(wm, __shfl_xor_sync(0xffffffffu, wm, off));
        // index resolution: lowest lane owning wm (lowest global index)
        unsigned bal = __ballot_sync(0xffffffffu, m == wm);
        int srcl = __ffs(bal) - 1;
        int widx = __shfl_sync(0xffffffffu, t * 16 + mi, srcl);
        if (lane == 0) {
            red_val[it & 1][wid] = wm;
            red_idx[it & 1][wid] = widx;
        }
        __syncthreads();

        // block-level: 16 warp results, all threads reduce redundantly
        float v = (lane < 16) ? red_val[it & 1][lane] : -1.0f;
        float vm = v;
        vm = fmaxf(vm, __shfl_xor_sync(0xffffffffu, vm, 8));
        vm = fmaxf(vm, __shfl_xor_sync(0xffffffffu, vm, 4));
        vm = fmaxf(vm, __shfl_xor_sync(0xffffffffu, vm, 2));
        vm = fmaxf(vm, __shfl_xor_sync(0xffffffffu, vm, 1));
        vm = fmaxf(vm, __shfl_xor_sync(0xffffffffu, vm, 16));
        unsigned bal2 = __ballot_sync(0xffffffffu, (lane < 16) && (v == vm));
        int wsrc = __ffs(bal2) - 1;
        const int idx = red_idx[it & 1][wsrc];           // LDS broadcast
        const float x = spx[idx], y = spy[idx], z = spz[idx];
        nlx = f2_pack(-x, -x);
        nly = f2_pack(-y, -y);
        nlz = f2_pack(-z, -z);
        if (t == 0) {
            g_new_idx[b * NPOINT + it] = idx;
            g_new_xyz[(size_t)(b * NPOINT + it) * 3 + 0] = x;
            g_new_xyz[(size_t)(b * NPOINT + it) * 3 + 1] = y;
            g_new_xyz[(size_t)(b * NPOINT + it) * 3 + 2] = z;
            out[OFF_IDX + b * NPOINT + it] = (float)idx;
            out[OFF_XYZ + (size_t)(b * NPOINT + it) * 3 + 0] = x;
            out[OFF_XYZ + (size_t)(b * NPOINT + it) * 3 + 1] = y;
            out[OFF_XYZ + (size_t)(b * NPOINT + it) * 3 + 2] = z;
        }
    }
}

// =============================================================================
// 2) Feature transpose [64, 65536] -> [65536, 64]
// =============================================================================
__global__ void transpose_kernel(const float* __restrict__ f) {
    __shared__ float tile[32][33];
    const int n0 = blockIdx.x * 32;
    const int c0 = blockIdx.y * 32;
    const int tx = threadIdx.x, ty = threadIdx.y;
#pragma unroll
    for (int i = 0; i < 4; i++)
        tile[ty + 8 * i][tx] = f[(size_t)(c0 + ty + 8 * i) * NTOT + (n0 + tx)];
    __syncthreads();
#pragma unroll
    for (int i = 0; i < 4; i++)
        g_featT[(size_t)(n0 + ty + 8 * i) * CIN + (c0 + tx)] = tile[tx][ty + 8 * i];
}

// =============================================================================
// 3) Ball query: one warp per center (unchanged; passes exactly).
// =============================================================================
__global__ void __launch_bounds__(256) ballq_kernel(const float* __restrict__ xyz,
                                                    float* __restrict__ out) {
    float* spx = dyn_smem;
    float* spy = spx + NPTS;
    float* spz = spy + NPTS;
    __shared__ int sm_ids[8][NSAMPLE];

    const int b = blockIdx.x >> 6;
    const int cblk = blockIdx.x & 63;
    const float* src = xyz + (size_t)b * NPTS * 3;

    for (int i = threadIdx.x; i < NPTS; i += 256) {
        spx[i] = src[3 * i + 0];
        spy[i] = src[3 * i + 1];
        spz[i] = src[3 * i + 2];
    }
    __syncthreads();

    const int w = threadIdx.x >> 5, lane = threadIdx.x & 31;
    const int gc = b * NPOINT + cblk * 8 + w;
    const float cx = g_new_xyz[(size_t)gc * 3 + 0];
    const float cy = g_new_xyz[(size_t)gc * 3 + 1];
    const float cz = g_new_xyz[(size_t)gc * 3 + 2];

    int count = 0, first = -1;
    for (int chunk = 0; chunk < NPTS / 32; ++chunk) {
        const int p = chunk * 32 + lane;
        float dx = __fsub_rn(cx, spx[p]);
        float dy = __fsub_rn(cy, spy[p]);
        float dz = __fsub_rn(cz, spz[p]);
        float d2 = __fadd_rn(__fadd_rn(__fmul_rn(dx, dx), __fmul_rn(dy, dy)),
                             __fmul_rn(dz, dz));
        const bool in = d2 < R2;
        const unsigned m = __ballot_sync(0xffffffffu, in);
        if (m) {
            if (first < 0) first = chunk * 32 + __ffs(m) - 1;
            if (in) {
                int rank = count + __popc(m & ((1u << lane) - 1u));
                if (rank < NSAMPLE) sm_ids[w][rank] = p;
            }
            count += __popc(m);
            if (count >= NSAMPLE) break;
        }
    }
    __syncwarp();
    if (first < 0) first = 0;
    const int id = (lane < count) ? sm_ids[w][lane] : first;
    g_sample_ids[(size_t)gc * NSAMPLE + lane] = id;
    out[OFF_SIDS + (size_t)gc * NSAMPLE + lane] = (float)id;
}

// =============================================================================
// 4) Fused gather + MLP(67->64->64->128, ReLU each) + max over samples.
//    One block = 8 centers = 256 sample columns, 512 threads, 4x8 thread tile.
//    Per warp: single o-tile (a-operand is an LDS broadcast).
// =============================================================================
__device__ __forceinline__ void fma_tile4(float acc[4][8],
                                          const float4& a0,
                                          const float4& b0, const float4& b1) {
    const float a[4]  = {a0.x, a0.y, a0.z, a0.w};
    const float bb[8] = {b0.x, b0.y, b0.z, b0.w, b1.x, b1.y, b1.z, b1.w};
#pragma unroll
    for (int i = 0; i < 4; i++)
#pragma unroll
        for (int j = 0; j < 8; j++) acc[i][j] += a[i] * bb[j];
}

template <int K, int LDA>
__device__ __forceinline__ void gemm4x8(const float* __restrict__ A,
                                        const float* __restrict__ Bm,
                                        int o0, int s0, float acc[4][8]) {
#pragma unroll
    for (int i = 0; i < 4; i++)
#pragma unroll
        for (int j = 0; j < 8; j++) acc[i][j] = 0.0f;

    float4 a0 = *(const float4*)&A[o0];
    float4 b0 = *(const float4*)&Bm[s0];
    float4 b1 = *(const float4*)&Bm[s0 + 4];
#pragma unroll 4
    for (int k = 0; k < K - 1; k++) {
        float4 na0 = *(const float4*)&A[(k + 1) * LDA + o0];
        float4 nb0 = *(const float4*)&Bm[(k + 1) * 256 + s0];
        float4 nb1 = *(const float4*)&Bm[(k + 1) * 256 + s0 + 4];
        fma_tile4(acc, a0, b0, b1);
        a0 = na0; b0 = nb0; b1 = nb1;
    }
    fma_tile4(acc, a0, b0, b1);
}

__global__ void __launch_bounds__(512) mlp_kernel(const float* __restrict__ xyz,
                                                  const float* __restrict__ W0,
                                                  const float* __restrict__ b0,
                                                  const float* __restrict__ W1,
                                                  const float* __restrict__ b1,
                                                  const float* __restrict__ W2,
                                                  const float* __restrict__ b2,
                                                  float* __restrict__ out) {
    float* sW0 = dyn_smem;          // [67][64]  (k-major)
    float* sb0 = sW0 + 67 * 64;
    float* sW1 = sb0 + 64;          // [64][64]
    float* sb1 = sW1 + 64 * 64;
    float* sW2 = sb1 + 64;          // [64][128]
    float* sb2 = sW2 + 64 * 128;
    float* X0  = sb2 + 128;         // [67][256]  (also reused as H2 [64][256])
    float* H1  = X0 + 67 * 256;     // [64][256]

    const int tid = threadIdx.x;
    const int b = blockIdx.x >> 6;
    const int cgrp = blockIdx.x & 63;

    // stage weights (transposed to k-major) + biases
    for (int i = tid; i < 67 * 64; i += 512) { int k = i >> 6, o = i & 63;  sW0[i] = W0[o * 67 + k]; }
    for (int i = tid; i < 64 * 64; i += 512) { int k = i >> 6, o = i & 63;  sW1[i] = W1[o * 64 + k]; }
    for (int i = tid; i < 64 * 128; i += 512){ int k = i >> 7, o = i & 127; sW2[i] = W2[o * 64 + k]; }
    if (tid < 64)  { sb0[tid] = b0[tid]; sb1[tid] = b1[tid]; }
    else if (tid >= 128 && tid < 256) { sb2[tid - 128] = b2[tid - 128]; }

    // gather: thread pair (s, s+256) splits one sample column
    {
        const int s = tid & 255;
        const int half = tid >> 8;
        const int cl = s >> 5;
        const int gc = b * NPOINT + cgrp * 8 + cl;
        const int pid = g_sample_ids[(size_t)gc * NSAMPLE + (s & 31)];
        if (half == 0) {
            const float* p = xyz + ((size_t)b * NPTS + pid) * 3;
            X0[0 * 256 + s] = p[0] - g_new_xyz[(size_t)gc * 3 + 0];
            X0[1 * 256 + s] = p[1] - g_new_xyz[(size_t)gc * 3 + 1];
            X0[2 * 256 + s] = p[2] - g_new_xyz[(size_t)gc * 3 + 2];
        }
        const float4* fp = (const float4*)(g_featT + ((size_t)b * NPTS + pid) * CIN + half * 32);
#pragma unroll
        for (int q = 0; q < 8; q++) {
            float4 v = fp[q];
            const int r = 3 + half * 32 + 4 * q;
            X0[(r + 0) * 256 + s] = v.x;
            X0[(r + 1) * 256 + s] = v.y;
            X0[(r + 2) * 256 + s] = v.z;
            X0[(r + 3) * 256 + s] = v.w;
        }
    }
    __syncthreads();

    const int ot = tid >> 5, st = tid & 31;   // ot uniform per warp
    const int o0 = ot * 4, s0 = st * 8;
    float acc[4][8];

    // layer 1: 67 -> 64
    gemm4x8<67, 64>(sW0, X0, o0, s0, acc);
#pragma unroll
    for (int i = 0; i < 4; i++) {
        const float bi = sb0[o0 + i];
        float* dst = &H1[(o0 + i) * 256 + s0];
#pragma unroll
        for (int j = 0; j < 8; j++) dst[j] = fmaxf(acc[i][j] + bi, 0.0f);
    }
    __syncthreads();

    // layer 2: 64 -> 64  (write H2 into X0 buffer)
    gemm4x8<64, 64>(sW1, H1, o0, s0, acc);
#pragma unroll
    for (int i = 0; i < 4; i++) {
        const float bi = sb1[o0 + i];
        float* dst = &X0[(o0 + i) * 256 + s0];
#pragma unroll
        for (int j = 0; j < 8; j++) dst[j] = fmaxf(acc[i][j] + bi, 0.0f);
    }
    __syncthreads();

    // layer 3: 64 -> 128 in two halves, max-over-samples fused in epilogue
#pragma unroll
    for (int half = 0; half < 2; ++half) {
        gemm4x8<64, 128>(sW2 + half * 64, X0, o0, s0, acc);
#pragma unroll
        for (int i = 0; i < 4; i++) {
            const float bi = sb2[half * 64 + o0 + i];
            float m = 0.0f;  // ReLU outputs are >= 0
#pragma unroll
            for (int j = 0; j < 8; j++) m = fmaxf(m, fmaxf(acc[i][j] + bi, 0.0f));
            m = fmaxf(m, __shfl_xor_sync(0xffffffffu, m, 1));
            m = fmaxf(m, __shfl_xor_sync(0xffffffffu, m, 2));
            if ((st & 3) == 0) {
                const int c = cgrp * 8 + (st >> 2);
                const int o = half * 64 + o0 + i;
                out[OFF_FEAT + ((size_t)b * 128 + o) * NPOINT + c] = m;
            }
        }
    }
}

// =============================================================================
extern "C" void kernel_launch(void* const* d_in, const int* in_sizes, int n_in,
                              void* d_out, int out_size) {
    const float* xyz  = (const float*)d_in[0];
    const float* feat = (const float*)d_in[1];
    const float* W0   = (const float*)d_in[3];
    const float* b0   = (const float*)d_in[4];
    const float* W1   = (const float*)d_in[5];
    const float* b1   = (const float*)d_in[6];
    const float* W2   = (const float*)d_in[7];
    const float* b2   = (const float*)d_in[8];
    float* out = (float*)d_out;

    const int smem_pts = 3 * NPTS * sizeof(float);                 // 98304
    const int smem_mlp = (67*64 + 64 + 64*64 + 64 + 64*128 + 128
                          + 67*256 + 64*256) * sizeof(float);      // 201472

    cudaFuncSetAttribute(fps_kernel,   cudaFuncAttributeMaxDynamicSharedMemorySize, smem_pts);
    cudaFuncSetAttribute(ballq_kernel, cudaFuncAttributeMaxDynamicSharedMemorySize, smem_pts);
    cudaFuncSetAttribute(mlp_kernel,   cudaFuncAttributeMaxDynamicSharedMemorySize, smem_mlp);

    fps_kernel<<<BATCH, 512, smem_pts>>>(xyz, out);
    transpose_kernel<<<dim3(NTOT / 32, CIN / 32), dim3(32, 8)>>>(feat);
    ballq_kernel<<<BATCH * (NPOINT / 8), 256, smem_pts>>>(xyz, out);
    mlp_kernel<<<BATCH * (NPOINT / 8), 512, smem_mlp>>>(xyz, W0, b0, W1, b1, W2, b2, out);
}

// round 6
// speedup vs baseline: 1.2075x; 1.2075x over previous
#include <cuda_runtime.h>
#include <cstdint>

// ---------------- problem constants (fixed by this input set) ----------------
#define BATCH    8
#define NPTS     8192
#define NTOT     65536
#define NPOINT   512
#define NSAMPLE  32
#define CIN      64
#define R2       (0.1f * 0.1f)

// d_out packing (float32), tuple flattened in return order:
#define OFF_XYZ   0                                   // new_xyz  [8,512,3]
#define OFF_IDX   (BATCH * NPOINT * 3)                // new_idx  [8,512]
#define OFF_FEAT  (OFF_IDX + BATCH * NPOINT)          // new_feat [8,128,512]
#define OFF_SIDS  (OFF_FEAT + BATCH * 128 * NPOINT)   // sample_ids [8,512,32]

// ---------------- scratch (device globals; no runtime allocation) ------------
__device__ int   g_new_idx[BATCH * NPOINT];
__device__ float g_new_xyz[BATCH * NPOINT * 3];
__device__ int   g_sample_ids[BATCH * NPOINT * NSAMPLE];
__device__ float g_featT[(size_t)NTOT * CIN];   // [n][c] transposed features

// ---------------- packed f32x2 helpers (bit-exact per-lane fp32) -------------
__device__ __forceinline__ unsigned long long f2_add(unsigned long long a, unsigned long long b) {
    unsigned long long r;
    asm("add.rn.f32x2 %0, %1, %2;" : "=l"(r) : "l"(a), "l"(b));
    return r;
}
__device__ __forceinline__ unsigned long long f2_mul(unsigned long long a, unsigned long long b) {
    unsigned long long r;
    asm("mul.rn.f32x2 %0, %1, %2;" : "=l"(r) : "l"(a), "l"(b));
    return r;
}
__device__ __forceinline__ unsigned long long f2_pack(float lo, float hi) {
    unsigned long long r;
    asm("mov.b64 %0, {%1, %2};" : "=l"(r) : "f"(lo), "f"(hi));
    return r;
}
__device__ __forceinline__ void f2_unpack(unsigned long long v, float& lo, float& hi) {
    asm("mov.b64 {%0, %1}, %2;" : "=f"(lo), "=f"(hi) : "l"(v));
}
__device__ __forceinline__ unsigned redux_max_u32(unsigned v) {
    unsigned r;
    asm("redux.sync.max.u32 %0, %1, 0xffffffff;" : "=r"(r) : "r"(v));
    return r;
}

extern __shared__ float dyn_smem[];

// =============================================================================
// 1) Furthest point sampling: 1 block per batch, 512 threads, 16 pts/thread.
//    Packed f32x2 distances (bit-exact (dx^2+dy^2)+dz^2). Max-reduction on
//    u32 bit patterns via redux.sync; only the winning thread resolves its
//    local argmax index + coords (from registers). Two barriers/iter.
// =============================================================================
__global__ void __launch_bounds__(512) fps_kernel(const float* __restrict__ xyz,
                                                  float* __restrict__ out) {
    float* spx = dyn_smem;
    float* spy = spx + NPTS;
    float* spz = spy + NPTS;
    __shared__ unsigned red_val[16];
    __shared__ float4 s_win;        // winner: x, y, z, idx-as-bits

    const int b = blockIdx.x;
    const int t = threadIdx.x;
    const float* src = xyz + (size_t)b * NPTS * 3;

    // load 16 consecutive points (48 floats = 12 float4)
    float f[48];
    {
        const float4* s4 = (const float4*)src;
        float4* f4 = (float4*)f;
#pragma unroll
        for (int i = 0; i < 12; i++) f4[i] = s4[t * 12 + i];
    }
    unsigned long long pxp[8], pyp[8], pzp[8];
    float dd[16];
#pragma unroll
    for (int a = 0; a < 8; a++) {
        pxp[a] = f2_pack(f[6 * a + 0], f[6 * a + 3]);
        pyp[a] = f2_pack(f[6 * a + 1], f[6 * a + 4]);
        pzp[a] = f2_pack(f[6 * a + 2], f[6 * a + 5]);
    }
#pragma unroll
    for (int j = 0; j < 16; j++) {
        dd[j] = 1e10f;
        spx[t * 16 + j] = f[3 * j + 0];
        spy[t * 16 + j] = f[3 * j + 1];
        spz[t * 16 + j] = f[3 * j + 2];
    }
    if (t == 0) {
        g_new_idx[b * NPOINT] = 0;
        g_new_xyz[(size_t)(b * NPOINT) * 3 + 0] = f[0];
        g_new_xyz[(size_t)(b * NPOINT) * 3 + 1] = f[1];
        g_new_xyz[(size_t)(b * NPOINT) * 3 + 2] = f[2];
        out[OFF_IDX + b * NPOINT] = 0.0f;
        out[OFF_XYZ + (size_t)(b * NPOINT) * 3 + 0] = f[0];
        out[OFF_XYZ + (size_t)(b * NPOINT) * 3 + 1] = f[1];
        out[OFF_XYZ + (size_t)(b * NPOINT) * 3 + 2] = f[2];
    }
    __syncthreads();

    // negated last-point coords, packed (x - l == x + (-l), exact)
    float lx0 = spx[0], ly0 = spy[0], lz0 = spz[0];
    unsigned long long nlx = f2_pack(-lx0, -lx0);
    unsigned long long nly = f2_pack(-ly0, -ly0);
    unsigned long long nlz = f2_pack(-lz0, -lz0);

    const int lane = t & 31, wid = t >> 5;

    for (int it = 1; it < NPOINT; ++it) {
        float m = 0.0f;   // dd >= 0 always, so u32 bit-pattern max == float max
#pragma unroll
        for (int a = 0; a < 8; a++) {
            unsigned long long dx = f2_add(pxp[a], nlx);
            unsigned long long dy = f2_add(pyp[a], nly);
            unsigned long long dz = f2_add(pzp[a], nlz);
            unsigned long long s  = f2_add(f2_add(f2_mul(dx, dx), f2_mul(dy, dy)),
                                           f2_mul(dz, dz));
            float d2l, d2h;
            f2_unpack(s, d2l, d2h);
            float n0 = fminf(dd[2 * a + 0], d2l);
            float n1 = fminf(dd[2 * a + 1], d2h);
            dd[2 * a + 0] = n0;
            dd[2 * a + 1] = n1;
            m = fmaxf(m, n0);
            m = fmaxf(m, n1);
        }
        const unsigned mu = __float_as_uint(m);
        const unsigned wm = redux_max_u32(mu);        // warp max, 1 instr
        if (lane == 0) red_val[wid] = wm;
        __syncthreads();

        const unsigned v = (lane < 16) ? red_val[lane] : 0u;
        const unsigned vm = redux_max_u32(v);         // block max (redundant/warp)
        const unsigned bal2 = __ballot_sync(0xffffffffu, v == vm);
        const int wsrc = __ffs(bal2) - 1;             // lowest winning warp
        if (wid == wsrc) {
            const unsigned balw = __ballot_sync(0xffffffffu, mu == vm);
            const int srcl = __ffs(balw) - 1;         // lowest winning lane
            if (lane == srcl) {
                int mi = 0;                            // lowest j with dd[j]==vm
#pragma unroll
                for (int j = 15; j >= 0; --j)
                    if (__float_as_uint(dd[j]) == vm) mi = j;
                const int a = mi >> 1;
                float xl, xh, yl, yh, zl, zh;
                f2_unpack(pxp[a], xl, xh);
                f2_unpack(pyp[a], yl, yh);
                f2_unpack(pzp[a], zl, zh);
                const float x = (mi & 1) ? xh : xl;
                const float y = (mi & 1) ? yh : yl;
                const float z = (mi & 1) ? zh : zl;
                s_win = make_float4(x, y, z, __int_as_float(t * 16 + mi));
            }
        }
        __syncthreads();

        const float4 w = s_win;
        nlx = f2_pack(-w.x, -w.x);
        nly = f2_pack(-w.y, -w.y);
        nlz = f2_pack(-w.z, -w.z);
        if (t == 0) {
            const int idx = __float_as_int(w.w);
            g_new_idx[b * NPOINT + it] = idx;
            g_new_xyz[(size_t)(b * NPOINT + it) * 3 + 0] = w.x;
            g_new_xyz[(size_t)(b * NPOINT + it) * 3 + 1] = w.y;
            g_new_xyz[(size_t)(b * NPOINT + it) * 3 + 2] = w.z;
            out[OFF_IDX + b * NPOINT + it] = (float)idx;
            out[OFF_XYZ + (size_t)(b * NPOINT + it) * 3 + 0] = w.x;
            out[OFF_XYZ + (size_t)(b * NPOINT + it) * 3 + 1] = w.y;
            out[OFF_XYZ + (size_t)(b * NPOINT + it) * 3 + 2] = w.z;
        }
    }
}

// =============================================================================
// 2) Feature transpose [64, 65536] -> [65536, 64]
// =============================================================================
__global__ void transpose_kernel(const float* __restrict__ f) {
    __shared__ float tile[32][33];
    const int n0 = blockIdx.x * 32;
    const int c0 = blockIdx.y * 32;
    const int tx = threadIdx.x, ty = threadIdx.y;
#pragma unroll
    for (int i = 0; i < 4; i++)
        tile[ty + 8 * i][tx] = f[(size_t)(c0 + ty + 8 * i) * NTOT + (n0 + tx)];
    __syncthreads();
#pragma unroll
    for (int i = 0; i < 4; i++)
        g_featT[(size_t)(n0 + ty + 8 * i) * CIN + (c0 + tx)] = tile[tx][ty + 8 * i];
}

// =============================================================================
// 3) Ball query: one warp per center (unchanged; passes exactly).
// =============================================================================
__global__ void __launch_bounds__(256) ballq_kernel(const float* __restrict__ xyz,
                                                    float* __restrict__ out) {
    float* spx = dyn_smem;
    float* spy = spx + NPTS;
    float* spz = spy + NPTS;
    __shared__ int sm_ids[8][NSAMPLE];

    const int b = blockIdx.x >> 6;
    const int cblk = blockIdx.x & 63;
    const float* src = xyz + (size_t)b * NPTS * 3;

    for (int i = threadIdx.x; i < NPTS; i += 256) {
        spx[i] = src[3 * i + 0];
        spy[i] = src[3 * i + 1];
        spz[i] = src[3 * i + 2];
    }
    __syncthreads();

    const int w = threadIdx.x >> 5, lane = threadIdx.x & 31;
    const int gc = b * NPOINT + cblk * 8 + w;
    const float cx = g_new_xyz[(size_t)gc * 3 + 0];
    const float cy = g_new_xyz[(size_t)gc * 3 + 1];
    const float cz = g_new_xyz[(size_t)gc * 3 + 2];

    int count = 0, first = -1;
    for (int chunk = 0; chunk < NPTS / 32; ++chunk) {
        const int p = chunk * 32 + lane;
        float dx = __fsub_rn(cx, spx[p]);
        float dy = __fsub_rn(cy, spy[p]);
        float dz = __fsub_rn(cz, spz[p]);
        float d2 = __fadd_rn(__fadd_rn(__fmul_rn(dx, dx), __fmul_rn(dy, dy)),
                             __fmul_rn(dz, dz));
        const bool in = d2 < R2;
        const unsigned m = __ballot_sync(0xffffffffu, in);
        if (m) {
            if (first < 0) first = chunk * 32 + __ffs(m) - 1;
            if (in) {
                int rank = count + __popc(m & ((1u << lane) - 1u));
                if (rank < NSAMPLE) sm_ids[w][rank] = p;
            }
            count += __popc(m);
            if (count >= NSAMPLE) break;
        }
    }
    __syncwarp();
    if (first < 0) first = 0;
    const int id = (lane < count) ? sm_ids[w][lane] : first;
    g_sample_ids[(size_t)gc * NSAMPLE + lane] = id;
    out[OFF_SIDS + (size_t)gc * NSAMPLE + lane] = (float)id;
}

// =============================================================================
// 4) Fused gather + MLP(67->64->64->128, ReLU each) + max over samples.
//    One block = 8 centers = 256 sample columns, 256 threads, 8x8 thread tile
//    (R3 configuration — measured at the fp32 FFMA roofline).
// =============================================================================
__device__ __forceinline__ void fma_tile(float acc[8][8],
                                         const float4& a0, const float4& a1,
                                         const float4& b0, const float4& b1) {
    const float a[8]  = {a0.x, a0.y, a0.z, a0.w, a1.x, a1.y, a1.z, a1.w};
    const float bb[8] = {b0.x, b0.y, b0.z, b0.w, b1.x, b1.y, b1.z, b1.w};
#pragma unroll
    for (int i = 0; i < 8; i++)
#pragma unroll
        for (int j = 0; j < 8; j++) acc[i][j] += a[i] * bb[j];
}

template <int K, int LDA>
__device__ __forceinline__ void gemm8x8(const float* __restrict__ A,
                                        const float* __restrict__ Bm,
                                        int o0, int s0, float acc[8][8]) {
#pragma unroll
    for (int i = 0; i < 8; i++)
#pragma unroll
        for (int j = 0; j < 8; j++) acc[i][j] = 0.0f;

    float4 a0 = *(const float4*)&A[o0];
    float4 a1 = *(const float4*)&A[o0 + 4];
    float4 b0 = *(const float4*)&Bm[s0];
    float4 b1 = *(const float4*)&Bm[s0 + 4];
#pragma unroll 4
    for (int k = 0; k < K - 1; k++) {
        float4 na0 = *(const float4*)&A[(k + 1) * LDA + o0];
        float4 na1 = *(const float4*)&A[(k + 1) * LDA + o0 + 4];
        float4 nb0 = *(const float4*)&Bm[(k + 1) * 256 + s0];
        float4 nb1 = *(const float4*)&Bm[(k + 1) * 256 + s0 + 4];
        fma_tile(acc, a0, a1, b0, b1);
        a0 = na0; a1 = na1; b0 = nb0; b1 = nb1;
    }
    fma_tile(acc, a0, a1, b0, b1);
}

__global__ void __launch_bounds__(256) mlp_kernel(const float* __restrict__ xyz,
                                                  const float* __restrict__ W0,
                                                  const float* __restrict__ b0,
                                                  const float* __restrict__ W1,
                                                  const float* __restrict__ b1,
                                                  const float* __restrict__ W2,
                                                  const float* __restrict__ b2,
                                                  float* __restrict__ out) {
    float* sW0 = dyn_smem;          // [67][64]  (k-major)
    float* sb0 = sW0 + 67 * 64;
    float* sW1 = sb0 + 64;          // [64][64]
    float* sb1 = sW1 + 64 * 64;
    float* sW2 = sb1 + 64;          // [64][128]
    float* sb2 = sW2 + 64 * 128;
    float* X0  = sb2 + 128;         // [67][256]  (also reused as H2 [64][256])
    float* H1  = X0 + 67 * 256;     // [64][256]

    const int tid = threadIdx.x;
    const int b = blockIdx.x >> 6;
    const int cgrp = blockIdx.x & 63;

    // stage weights (transposed to k-major) + biases
    for (int i = tid; i < 67 * 64; i += 256) { int k = i >> 6, o = i & 63;  sW0[i] = W0[o * 67 + k]; }
    for (int i = tid; i < 64 * 64; i += 256) { int k = i >> 6, o = i & 63;  sW1[i] = W1[o * 64 + k]; }
    for (int i = tid; i < 64 * 128; i += 256){ int k = i >> 7, o = i & 127; sW2[i] = W2[o * 64 + k]; }
    if (tid < 64)  { sb0[tid] = b0[tid]; sb1[tid] = b1[tid]; }
    if (tid < 128) { sb2[tid] = b2[tid]; }

    // gather: each thread owns one sample column
    {
        const int s = tid;
        const int cl = s >> 5;
        const int gc = b * NPOINT + cgrp * 8 + cl;
        const int pid = g_sample_ids[(size_t)gc * NSAMPLE + (s & 31)];
        const float* p = xyz + ((size_t)b * NPTS + pid) * 3;
        const float cx = g_new_xyz[(size_t)gc * 3 + 0];
        const float cy = g_new_xyz[(size_t)gc * 3 + 1];
        const float cz = g_new_xyz[(size_t)gc * 3 + 2];
        X0[0 * 256 + s] = p[0] - cx;
        X0[1 * 256 + s] = p[1] - cy;
        X0[2 * 256 + s] = p[2] - cz;
        const float4* fp = (const float4*)(g_featT + ((size_t)b * NPTS + pid) * CIN);
#pragma unroll
        for (int q = 0; q < 16; q++) {
            float4 v = fp[q];
            X0[(3 + 4 * q + 0) * 256 + s] = v.x;
            X0[(3 + 4 * q + 1) * 256 + s] = v.y;
            X0[(3 + 4 * q + 2) * 256 + s] = v.z;
            X0[(3 + 4 * q + 3) * 256 + s] = v.w;
        }
    }
    __syncthreads();

    const int ot = tid >> 5, st = tid & 31;
    const int o0 = ot * 8, s0 = st * 8;
    float acc[8][8];

    // layer 1: 67 -> 64
    gemm8x8<67, 64>(sW0, X0, o0, s0, acc);
#pragma unroll
    for (int i = 0; i < 8; i++) {
        const float bi = sb0[o0 + i];
        float* dst = &H1[(o0 + i) * 256 + s0];
#pragma unroll
        for (int j = 0; j < 8; j++) dst[j] = fmaxf(acc[i][j] + bi, 0.0f);
    }
    __syncthreads();

    // layer 2: 64 -> 64  (write H2 into X0 buffer)
    gemm8x8<64, 64>(sW1, H1, o0, s0, acc);
#pragma unroll
    for (int i = 0; i < 8; i++) {
        const float bi = sb1[o0 + i];
        float* dst = &X0[(o0 + i) * 256 + s0];
#pragma unroll
        for (int j = 0; j < 8; j++) dst[j] = fmaxf(acc[i][j] + bi, 0.0f);
    }
    __syncthreads();

    // layer 3: 64 -> 128 in two halves, max-over-samples fused in epilogue
#pragma unroll
    for (int half = 0; half < 2; ++half) {
        gemm8x8<64, 128>(sW2 + half * 64, X0, o0, s0, acc);
#pragma unroll
        for (int i = 0; i < 8; i++) {
            const float bi = sb2[half * 64 + o0 + i];
            float m = 0.0f;  // ReLU outputs are >= 0
#pragma unroll
            for (int j = 0; j < 8; j++) m = fmaxf(m, fmaxf(acc[i][j] + bi, 0.0f));
            m = fmaxf(m, __shfl_xor_sync(0xffffffffu, m, 1));
            m = fmaxf(m, __shfl_xor_sync(0xffffffffu, m, 2));
            if ((st & 3) == 0) {
                const int c = cgrp * 8 + (st >> 2);
                const int o = half * 64 + o0 + i;
                out[OFF_FEAT + ((size_t)b * 128 + o) * NPOINT + c] = m;
            }
        }
    }
}

// =============================================================================
extern "C" void kernel_launch(void* const* d_in, const int* in_sizes, int n_in,
                              void* d_out, int out_size) {
    const float* xyz  = (const float*)d_in[0];
    const float* feat = (const float*)d_in[1];
    const float* W0   = (const float*)d_in[3];
    const float* b0   = (const float*)d_in[4];
    const float* W1   = (const float*)d_in[5];
    const float* b1   = (const float*)d_in[6];
    const float* W2   = (const float*)d_in[7];
    const float* b2   = (const float*)d_in[8];
    float* out = (float*)d_out;

    const int smem_pts = 3 * NPTS * sizeof(float);                 // 98304
    const int smem_mlp = (67*64 + 64 + 64*64 + 64 + 64*128 + 128
                          + 67*256 + 64*256) * sizeof(float);      // 201472

    cudaFuncSetAttribute(fps_kernel,   cudaFuncAttributeMaxDynamicSharedMemorySize, smem_pts);
    cudaFuncSetAttribute(ballq_kernel, cudaFuncAttributeMaxDynamicSharedMemorySize, smem_pts);
    cudaFuncSetAttribute(mlp_kernel,   cudaFuncAttributeMaxDynamicSharedMemorySize, smem_mlp);

    fps_kernel<<<BATCH, 512, smem_pts>>>(xyz, out);
    transpose_kernel<<<dim3(NTOT / 32, CIN / 32), dim3(32, 8)>>>(feat);
    ballq_kernel<<<BATCH * (NPOINT / 8), 256, smem_pts>>>(xyz, out);
    mlp_kernel<<<BATCH * (NPOINT / 8), 256, smem_mlp>>>(xyz, W0, b0, W1, b1, W2, b2, out);
}

// round 7
// speedup vs baseline: 1.2121x; 1.0037x over previous
#include <cuda_runtime.h>
#include <cstdint>

// ---------------- problem constants (fixed by this input set) ----------------
#define BATCH    8
#define NPTS     8192
#define NTOT     65536
#define NPOINT   512
#define NSAMPLE  32
#define CIN      64
#define R2       (0.1f * 0.1f)

// d_out packing (float32), tuple flattened in return order:
#define OFF_XYZ   0                                   // new_xyz  [8,512,3]
#define OFF_IDX   (BATCH * NPOINT * 3)                // new_idx  [8,512]
#define OFF_FEAT  (OFF_IDX + BATCH * NPOINT)          // new_feat [8,128,512]
#define OFF_SIDS  (OFF_FEAT + BATCH * 128 * NPOINT)   // sample_ids [8,512,32]

// ---------------- scratch (device globals; no runtime allocation) ------------
__device__ int   g_new_idx[BATCH * NPOINT];
__device__ float g_new_xyz[BATCH * NPOINT * 3];
__device__ int   g_sample_ids[BATCH * NPOINT * NSAMPLE];
__device__ float g_featT[(size_t)NTOT * CIN];   // [n][c] transposed features

// ---------------- packed f32x2 helpers (bit-exact per-lane fp32) -------------
__device__ __forceinline__ unsigned long long f2_add(unsigned long long a, unsigned long long b) {
    unsigned long long r;
    asm("add.rn.f32x2 %0, %1, %2;" : "=l"(r) : "l"(a), "l"(b));
    return r;
}
__device__ __forceinline__ unsigned long long f2_mul(unsigned long long a, unsigned long long b) {
    unsigned long long r;
    asm("mul.rn.f32x2 %0, %1, %2;" : "=l"(r) : "l"(a), "l"(b));
    return r;
}
__device__ __forceinline__ unsigned long long f2_pack(float lo, float hi) {
    unsigned long long r;
    asm("mov.b64 %0, {%1, %2};" : "=l"(r) : "f"(lo), "f"(hi));
    return r;
}
__device__ __forceinline__ void f2_unpack(unsigned long long v, float& lo, float& hi) {
    asm("mov.b64 {%0, %1}, %2;" : "=f"(lo), "=f"(hi) : "l"(v));
}
__device__ __forceinline__ unsigned redux_max_u32(unsigned v) {
    unsigned r;
    asm("redux.sync.max.u32 %0, %1, 0xffffffff;" : "=r"(r) : "r"(v));
    return r;
}

extern __shared__ float dyn_smem[];

// =============================================================================
// 1) FPS (blocks 0..7, serial per batch) + feature transpose (blocks 8..263,
//    independent work that hides under FPS's 8-SM serial phase).
// =============================================================================
__global__ void __launch_bounds__(512) fps_tr_kernel(const float* __restrict__ xyz,
                                                     const float* __restrict__ feat,
                                                     float* __restrict__ out) {
    const int t = threadIdx.x;

    if (blockIdx.x >= BATCH) {
        // ---------------- transpose path: 16 tiles of 32x32 per block --------
        float* tile = dyn_smem;                       // 32*33 floats
        const int bb = blockIdx.x - BATCH;            // 0..255
        const int tx = t & 31, ty = t >> 5;           // ty 0..15
        for (int ti = 0; ti < 16; ++ti) {
            const int tile_id = bb * 16 + ti;         // 0..4095
            const int n0 = (tile_id & 2047) * 32;
            const int c0 = (tile_id >> 11) * 32;
            __syncthreads();
            tile[ty * 33 + tx]        = feat[(size_t)(c0 + ty) * NTOT + (n0 + tx)];
            tile[(ty + 16) * 33 + tx] = feat[(size_t)(c0 + ty + 16) * NTOT + (n0 + tx)];
            __syncthreads();
            g_featT[(size_t)(n0 + ty) * CIN + (c0 + tx)]      = tile[tx * 33 + ty];
            g_featT[(size_t)(n0 + ty + 16) * CIN + (c0 + tx)] = tile[tx * 33 + ty + 16];
        }
        return;
    }

    // ---------------- FPS path: 512 threads, 16 pts/thread -------------------
    float* spx = dyn_smem;
    float* spy = spx + NPTS;
    float* spz = spy + NPTS;
    __shared__ unsigned red_val[16];
    __shared__ float4 s_win;        // winner: x, y, z, idx-as-bits

    const int b = blockIdx.x;
    const float* src = xyz + (size_t)b * NPTS * 3;

    // load 16 consecutive points (48 floats = 12 float4)
    float f[48];
    {
        const float4* s4 = (const float4*)src;
        float4* f4 = (float4*)f;
#pragma unroll
        for (int i = 0; i < 12; i++) f4[i] = s4[t * 12 + i];
    }
    unsigned long long pxp[8], pyp[8], pzp[8];
    float dd[16];
#pragma unroll
    for (int a = 0; a < 8; a++) {
        pxp[a] = f2_pack(f[6 * a + 0], f[6 * a + 3]);
        pyp[a] = f2_pack(f[6 * a + 1], f[6 * a + 4]);
        pzp[a] = f2_pack(f[6 * a + 2], f[6 * a + 5]);
    }
#pragma unroll
    for (int j = 0; j < 16; j++) {
        dd[j] = 1e10f;
        spx[t * 16 + j] = f[3 * j + 0];
        spy[t * 16 + j] = f[3 * j + 1];
        spz[t * 16 + j] = f[3 * j + 2];
    }
    if (t == 0) {
        g_new_idx[b * NPOINT] = 0;
        g_new_xyz[(size_t)(b * NPOINT) * 3 + 0] = f[0];
        g_new_xyz[(size_t)(b * NPOINT) * 3 + 1] = f[1];
        g_new_xyz[(size_t)(b * NPOINT) * 3 + 2] = f[2];
        out[OFF_IDX + b * NPOINT] = 0.0f;
        out[OFF_XYZ + (size_t)(b * NPOINT) * 3 + 0] = f[0];
        out[OFF_XYZ + (size_t)(b * NPOINT) * 3 + 1] = f[1];
        out[OFF_XYZ + (size_t)(b * NPOINT) * 3 + 2] = f[2];
    }
    __syncthreads();

    // negated last-point coords, packed (x - l == x + (-l), exact)
    float lx0 = spx[0], ly0 = spy[0], lz0 = spz[0];
    unsigned long long nlx = f2_pack(-lx0, -lx0);
    unsigned long long nly = f2_pack(-ly0, -ly0);
    unsigned long long nlz = f2_pack(-lz0, -lz0);

    const int lane = t & 31, wid = t >> 5;

    for (int it = 1; it < NPOINT; ++it) {
#pragma unroll
        for (int a = 0; a < 8; a++) {
            unsigned long long dx = f2_add(pxp[a], nlx);
            unsigned long long dy = f2_add(pyp[a], nly);
            unsigned long long dz = f2_add(pzp[a], nlz);
            unsigned long long s  = f2_add(f2_add(f2_mul(dx, dx), f2_mul(dy, dy)),
                                           f2_mul(dz, dz));
            float d2l, d2h;
            f2_unpack(s, d2l, d2h);
            dd[2 * a + 0] = fminf(dd[2 * a + 0], d2l);
            dd[2 * a + 1] = fminf(dd[2 * a + 1], d2h);
        }
        // log-depth max over the 16 residual distances
        float m8[8];
#pragma unroll
        for (int j = 0; j < 8; j++) m8[j] = fmaxf(dd[2 * j], dd[2 * j + 1]);
#pragma unroll
        for (int j = 0; j < 4; j++) m8[j] = fmaxf(m8[j], m8[j + 4]);
        m8[0] = fmaxf(m8[0], m8[2]);
        m8[1] = fmaxf(m8[1], m8[3]);
        const float m = fmaxf(m8[0], m8[1]);   // dd >= 0: u32-bit max == float max

        const unsigned mu = __float_as_uint(m);
        const unsigned wm = redux_max_u32(mu);        // warp max, 1 instr
        if (lane == 0) red_val[wid] = wm;
        __syncthreads();

        const unsigned v = (lane < 16) ? red_val[lane] : 0u;
        const unsigned vm = redux_max_u32(v);         // block max (redundant/warp)
        const unsigned bal2 = __ballot_sync(0xffffffffu, v == vm);
        const int wsrc = __ffs(bal2) - 1;             // lowest winning warp
        if (wid == wsrc) {
            const unsigned balw = __ballot_sync(0xffffffffu, mu == vm);
            const int srcl = __ffs(balw) - 1;         // lowest winning lane
            if (lane == srcl) {
                int mi = 0;                            // lowest j with dd[j]==vm
#pragma unroll
                for (int j = 15; j >= 0; --j)
                    if (__float_as_uint(dd[j]) == vm) mi = j;
                const int a = mi >> 1;
                float xl, xh, yl, yh, zl, zh;
                f2_unpack(pxp[a], xl, xh);
                f2_unpack(pyp[a], yl, yh);
                f2_unpack(pzp[a], zl, zh);
                const float x = (mi & 1) ? xh : xl;
                const float y = (mi & 1) ? yh : yl;
                const float z = (mi & 1) ? zh : zl;
                s_win = make_float4(x, y, z, __int_as_float(t * 16 + mi));
            }
        }
        __syncthreads();

        const float4 w = s_win;
        nlx = f2_pack(-w.x, -w.x);
        nly = f2_pack(-w.y, -w.y);
        nlz = f2_pack(-w.z, -w.z);
        if (t == 0) {
            const int idx = __float_as_int(w.w);
            g_new_idx[b * NPOINT + it] = idx;
            g_new_xyz[(size_t)(b * NPOINT + it) * 3 + 0] = w.x;
            g_new_xyz[(size_t)(b * NPOINT + it) * 3 + 1] = w.y;
            g_new_xyz[(size_t)(b * NPOINT + it) * 3 + 2] = w.z;
            out[OFF_IDX + b * NPOINT + it] = (float)idx;
            out[OFF_XYZ + (size_t)(b * NPOINT + it) * 3 + 0] = w.x;
            out[OFF_XYZ + (size_t)(b * NPOINT + it) * 3 + 1] = w.y;
            out[OFF_XYZ + (size_t)(b * NPOINT + it) * 3 + 2] = w.z;
        }
    }
}

// =============================================================================
// 3) Ball query: one warp per center (unchanged; passes exactly).
// =============================================================================
__global__ void __launch_bounds__(256) ballq_kernel(const float* __restrict__ xyz,
                                                    float* __restrict__ out) {
    float* spx = dyn_smem;
    float* spy = spx + NPTS;
    float* spz = spy + NPTS;
    __shared__ int sm_ids[8][NSAMPLE];

    const int b = blockIdx.x >> 6;
    const int cblk = blockIdx.x & 63;
    const float* src = xyz + (size_t)b * NPTS * 3;

    for (int i = threadIdx.x; i < NPTS; i += 256) {
        spx[i] = src[3 * i + 0];
        spy[i] = src[3 * i + 1];
        spz[i] = src[3 * i + 2];
    }
    __syncthreads();

    const int w = threadIdx.x >> 5, lane = threadIdx.x & 31;
    const int gc = b * NPOINT + cblk * 8 + w;
    const float cx = g_new_xyz[(size_t)gc * 3 + 0];
    const float cy = g_new_xyz[(size_t)gc * 3 + 1];
    const float cz = g_new_xyz[(size_t)gc * 3 + 2];

    int count = 0, first = -1;
    for (int chunk = 0; chunk < NPTS / 32; ++chunk) {
        const int p = chunk * 32 + lane;
        float dx = __fsub_rn(cx, spx[p]);
        float dy = __fsub_rn(cy, spy[p]);
        float dz = __fsub_rn(cz, spz[p]);
        float d2 = __fadd_rn(__fadd_rn(__fmul_rn(dx, dx), __fmul_rn(dy, dy)),
                             __fmul_rn(dz, dz));
        const bool in = d2 < R2;
        const unsigned m = __ballot_sync(0xffffffffu, in);
        if (m) {
            if (first < 0) first = chunk * 32 + __ffs(m) - 1;
            if (in) {
                int rank = count + __popc(m & ((1u << lane) - 1u));
                if (rank < NSAMPLE) sm_ids[w][rank] = p;
            }
            count += __popc(m);
            if (count >= NSAMPLE) break;
        }
    }
    __syncwarp();
    if (first < 0) first = 0;
    const int id = (lane < count) ? sm_ids[w][lane] : first;
    g_sample_ids[(size_t)gc * NSAMPLE + lane] = id;
    out[OFF_SIDS + (size_t)gc * NSAMPLE + lane] = (float)id;
}

// =============================================================================
// 4) Fused gather + MLP(67->64->64->128, ReLU each) + max over samples.
//    256 threads, 8x8 register tile. Each thread owns columns
//    [st*4, st*4+4) and [128+st*4, 128+st*4+4): all LDS/STS.128 are at 16B
//    lane stride -> conflict-free shared memory.
// =============================================================================
__device__ __forceinline__ void fma_tile(float acc[8][8],
                                         const float4& a0, const float4& a1,
                                         const float4& b0, const float4& b1) {
    const float a[8]  = {a0.x, a0.y, a0.z, a0.w, a1.x, a1.y, a1.z, a1.w};
    const float bb[8] = {b0.x, b0.y, b0.z, b0.w, b1.x, b1.y, b1.z, b1.w};
#pragma unroll
    for (int i = 0; i < 8; i++)
#pragma unroll
        for (int j = 0; j < 8; j++) acc[i][j] += a[i] * bb[j];
}

// acc[i][0..3] -> cols c0..c0+3 ; acc[i][4..7] -> cols c1..c1+3
template <int K, int LDA>
__device__ __forceinline__ void gemm8x8(const float* __restrict__ A,
                                        const float* __restrict__ Bm,
                                        int o0, int c0, int c1, float acc[8][8]) {
#pragma unroll
    for (int i = 0; i < 8; i++)
#pragma unroll
        for (int j = 0; j < 8; j++) acc[i][j] = 0.0f;

    float4 a0 = *(const float4*)&A[o0];
    float4 a1 = *(const float4*)&A[o0 + 4];
    float4 b0 = *(const float4*)&Bm[c0];
    float4 b1 = *(const float4*)&Bm[c1];
#pragma unroll 4
    for (int k = 0; k < K - 1; k++) {
        float4 na0 = *(const float4*)&A[(k + 1) * LDA + o0];
        float4 na1 = *(const float4*)&A[(k + 1) * LDA + o0 + 4];
        float4 nb0 = *(const float4*)&Bm[(k + 1) * 256 + c0];
        float4 nb1 = *(const float4*)&Bm[(k + 1) * 256 + c1];
        fma_tile(acc, a0, a1, b0, b1);
        a0 = na0; a1 = na1; b0 = nb0; b1 = nb1;
    }
    fma_tile(acc, a0, a1, b0, b1);
}

__global__ void __launch_bounds__(256) mlp_kernel(const float* __restrict__ xyz,
                                                  const float* __restrict__ W0,
                                                  const float* __restrict__ b0,
                                                  const float* __restrict__ W1,
                                                  const float* __restrict__ b1,
                                                  const float* __restrict__ W2,
                                                  const float* __restrict__ b2,
                                                  float* __restrict__ out) {
    float* sW0 = dyn_smem;          // [67][64]  (k-major)
    float* sb0 = sW0 + 67 * 64;
    float* sW1 = sb0 + 64;          // [64][64]
    float* sb1 = sW1 + 64 * 64;
    float* sW2 = sb1 + 64;          // [64][128]
    float* sb2 = sW2 + 64 * 128;
    float* X0  = sb2 + 128;         // [67][256]  (also reused as H2 [64][256])
    float* H1  = X0 + 67 * 256;     // [64][256]

    const int tid = threadIdx.x;
    const int b = blockIdx.x >> 6;
    const int cgrp = blockIdx.x & 63;

    // stage weights (transposed to k-major) + biases
    for (int i = tid; i < 67 * 64; i += 256) { int k = i >> 6, o = i & 63;  sW0[i] = W0[o * 67 + k]; }
    for (int i = tid; i < 64 * 64; i += 256) { int k = i >> 6, o = i & 63;  sW1[i] = W1[o * 64 + k]; }
    for (int i = tid; i < 64 * 128; i += 256){ int k = i >> 7, o = i & 127; sW2[i] = W2[o * 64 + k]; }
    if (tid < 64)  { sb0[tid] = b0[tid]; sb1[tid] = b1[tid]; }
    if (tid < 128) { sb2[tid] = b2[tid]; }

    // gather: each thread owns one sample column
    {
        const int s = tid;
        const int cl = s >> 5;
        const int gc = b * NPOINT + cgrp * 8 + cl;
        const int pid = g_sample_ids[(size_t)gc * NSAMPLE + (s & 31)];
        const float* p = xyz + ((size_t)b * NPTS + pid) * 3;
        const float cx = g_new_xyz[(size_t)gc * 3 + 0];
        const float cy = g_new_xyz[(size_t)gc * 3 + 1];
        const float cz = g_new_xyz[(size_t)gc * 3 + 2];
        X0[0 * 256 + s] = p[0] - cx;
        X0[1 * 256 + s] = p[1] - cy;
        X0[2 * 256 + s] = p[2] - cz;
        const float4* fp = (const float4*)(g_featT + ((size_t)b * NPTS + pid) * CIN);
#pragma unroll
        for (int q = 0; q < 16; q++) {
            float4 v = fp[q];
            X0[(3 + 4 * q + 0) * 256 + s] = v.x;
            X0[(3 + 4 * q + 1) * 256 + s] = v.y;
            X0[(3 + 4 * q + 2) * 256 + s] = v.z;
            X0[(3 + 4 * q + 3) * 256 + s] = v.w;
        }
    }
    __syncthreads();

    const int ot = tid >> 5, st = tid & 31;
    const int o0 = ot * 8;
    const int c0 = st * 4, c1 = 128 + st * 4;
    float acc[8][8];

    // layer 1: 67 -> 64
    gemm8x8<67, 64>(sW0, X0, o0, c0, c1, acc);
#pragma unroll
    for (int i = 0; i < 8; i++) {
        const float bi = sb0[o0 + i];
        float4 r0 = make_float4(fmaxf(acc[i][0] + bi, 0.0f), fmaxf(acc[i][1] + bi, 0.0f),
                                fmaxf(acc[i][2] + bi, 0.0f), fmaxf(acc[i][3] + bi, 0.0f));
        float4 r1 = make_float4(fmaxf(acc[i][4] + bi, 0.0f), fmaxf(acc[i][5] + bi, 0.0f),
                                fmaxf(acc[i][6] + bi, 0.0f), fmaxf(acc[i][7] + bi, 0.0f));
        *(float4*)&H1[(o0 + i) * 256 + c0] = r0;
        *(float4*)&H1[(o0 + i) * 256 + c1] = r1;
    }
    __syncthreads();

    // layer 2: 64 -> 64  (write H2 into X0 buffer)
    gemm8x8<64, 64>(sW1, H1, o0, c0, c1, acc);
#pragma unroll
    for (int i = 0; i < 8; i++) {
        const float bi = sb1[o0 + i];
        float4 r0 = make_float4(fmaxf(acc[i][0] + bi, 0.0f), fmaxf(acc[i][1] + bi, 0.0f),
                                fmaxf(acc[i][2] + bi, 0.0f), fmaxf(acc[i][3] + bi, 0.0f));
        float4 r1 = make_float4(fmaxf(acc[i][4] + bi, 0.0f), fmaxf(acc[i][5] + bi, 0.0f),
                                fmaxf(acc[i][6] + bi, 0.0f), fmaxf(acc[i][7] + bi, 0.0f));
        *(float4*)&X0[(o0 + i) * 256 + c0] = r0;
        *(float4*)&X0[(o0 + i) * 256 + c1] = r1;
    }
    __syncthreads();

    // layer 3: 64 -> 128 in two halves, max-over-samples fused in epilogue.
    // Thread's cols c0..c0+3 belong to center g = st>>3; c1..c1+3 to center 4+g.
    const int g = st >> 3;
#pragma unroll
    for (int half = 0; half < 2; ++half) {
        gemm8x8<64, 128>(sW2 + half * 64, X0, o0, c0, c1, acc);
#pragma unroll
        for (int i = 0; i < 8; i++) {
            const float bi = sb2[half * 64 + o0 + i];
            float m0 = 0.0f, m1 = 0.0f;   // ReLU outputs are >= 0
#pragma unroll
            for (int j = 0; j < 4; j++) {
                m0 = fmaxf(m0, fmaxf(acc[i][j] + bi, 0.0f));
                m1 = fmaxf(m1, fmaxf(acc[i][4 + j] + bi, 0.0f));
            }
            m0 = fmaxf(m0, __shfl_xor_sync(0xffffffffu, m0, 1));
            m1 = fmaxf(m1, __shfl_xor_sync(0xffffffffu, m1, 1));
            m0 = fmaxf(m0, __shfl_xor_sync(0xffffffffu, m0, 2));
            m1 = fmaxf(m1, __shfl_xor_sync(0xffffffffu, m1, 2));
            m0 = fmaxf(m0, __shfl_xor_sync(0xffffffffu, m0, 4));
            m1 = fmaxf(m1, __shfl_xor_sync(0xffffffffu, m1, 4));
            if ((st & 7) == 0) {
                const int o = half * 64 + o0 + i;
                out[OFF_FEAT + ((size_t)b * 128 + o) * NPOINT + cgrp * 8 + g]     = m0;
                out[OFF_FEAT + ((size_t)b * 128 + o) * NPOINT + cgrp * 8 + 4 + g] = m1;
            }
        }
    }
}

// =============================================================================
extern "C" void kernel_launch(void* const* d_in, const int* in_sizes, int n_in,
                              void* d_out, int out_size) {
    const float* xyz  = (const float*)d_in[0];
    const float* feat = (const float*)d_in[1];
    const float* W0   = (const float*)d_in[3];
    const float* b0   = (const float*)d_in[4];
    const float* W1   = (const float*)d_in[5];
    const float* b1   = (const float*)d_in[6];
    const float* W2   = (const float*)d_in[7];
    const float* b2   = (const float*)d_in[8];
    float* out = (float*)d_out;

    const int smem_pts = 3 * NPTS * sizeof(float);                 // 98304
    const int smem_mlp = (67*64 + 64 + 64*64 + 64 + 64*128 + 128
                          + 67*256 + 64*256) * sizeof(float);      // 201472

    cudaFuncSetAttribute(fps_tr_kernel, cudaFuncAttributeMaxDynamicSharedMemorySize, smem_pts);
    cudaFuncSetAttribute(ballq_kernel,  cudaFuncAttributeMaxDynamicSharedMemorySize, smem_pts);
    cudaFuncSetAttribute(mlp_kernel,    cudaFuncAttributeMaxDynamicSharedMemorySize, smem_mlp);

    fps_tr_kernel<<<BATCH + 256, 512, smem_pts>>>(xyz, feat, out);
    ballq_kernel<<<BATCH * (NPOINT / 8), 256, smem_pts>>>(xyz, out);
    mlp_kernel<<<BATCH * (NPOINT / 8), 256, smem_mlp>>>(xyz, W0, b0, W1, b1, W2, b2, out);
}

// round 9
// speedup vs baseline: 1.3646x; 1.1258x over previous
#include <cuda_runtime.h>
#include <cstdint>

// ---------------- problem constants (fixed by this input set) ----------------
#define BATCH    8
#define NPTS     8192
#define NTOT     65536
#define NPOINT   512
#define NSAMPLE  32
#define CIN      64
#define R2       (0.1f * 0.1f)

// d_out packing (float32), tuple flattened in return order:
#define OFF_XYZ   0                                   // new_xyz  [8,512,3]
#define OFF_IDX   (BATCH * NPOINT * 3)                // new_idx  [8,512]
#define OFF_FEAT  (OFF_IDX + BATCH * NPOINT)          // new_feat [8,128,512]
#define OFF_SIDS  (OFF_FEAT + BATCH * 128 * NPOINT)   // sample_ids [8,512,32]

// ---------------- scratch (device globals; no runtime allocation) ------------
__device__ int   g_new_idx[BATCH * NPOINT];
__device__ float g_new_xyz[BATCH * NPOINT * 3];
__device__ int   g_sample_ids[BATCH * NPOINT * NSAMPLE];
__device__ float g_featT[(size_t)NTOT * CIN];   // [n][c] transposed features

// ---------------- packed f32x2 helpers (bit-exact per-lane fp32) -------------
__device__ __forceinline__ unsigned long long f2_add(unsigned long long a, unsigned long long b) {
    unsigned long long r;
    asm("add.rn.f32x2 %0, %1, %2;" : "=l"(r) : "l"(a), "l"(b));
    return r;
}
__device__ __forceinline__ unsigned long long f2_mul(unsigned long long a, unsigned long long b) {
    unsigned long long r;
    asm("mul.rn.f32x2 %0, %1, %2;" : "=l"(r) : "l"(a), "l"(b));
    return r;
}
__device__ __forceinline__ unsigned long long f2_pack(float lo, float hi) {
    unsigned long long r;
    asm("mov.b64 %0, {%1, %2};" : "=l"(r) : "f"(lo), "f"(hi));
    return r;
}
__device__ __forceinline__ void f2_unpack(unsigned long long v, float& lo, float& hi) {
    asm("mov.b64 {%0, %1}, %2;" : "=f"(lo), "=f"(hi) : "l"(v));
}
__device__ __forceinline__ unsigned redux_max_u32(unsigned v) {
    unsigned r;
    asm("redux.sync.max.u32 %0, %1, 0xffffffff;" : "=r"(r) : "r"(v));
    return r;
}

extern __shared__ float dyn_smem[];

// =============================================================================
// 1) FPS (blocks 0..7, serial per batch) + feature transpose (blocks 8..263).
//    FPS: 512 threads, 16 pts/thread, packed f32x2 exact distances,
//    incremental per-thread argmax, ONE __syncthreads per iteration:
//    warps publish packed (max_bits, global_idx) u64; all warps redundantly
//    reduce the 16 entries; winner coords via one broadcast LDS.128.
// =============================================================================
__global__ void __launch_bounds__(512) fps_tr_kernel(const float* __restrict__ xyz,
                                                     const float* __restrict__ feat,
                                                     float* __restrict__ out) {
    const int t = threadIdx.x;

    if (blockIdx.x >= BATCH) {
        // ---------------- transpose path: 16 tiles of 32x32 per block --------
        float* tile = dyn_smem;                       // 32*33 floats
        const int bb = blockIdx.x - BATCH;            // 0..255
        const int tx = t & 31, ty = t >> 5;           // ty 0..15
        for (int ti = 0; ti < 16; ++ti) {
            const int tile_id = bb * 16 + ti;         // 0..4095
            const int n0 = (tile_id & 2047) * 32;
            const int c0 = (tile_id >> 11) * 32;
            __syncthreads();
            tile[ty * 33 + tx]        = feat[(size_t)(c0 + ty) * NTOT + (n0 + tx)];
            tile[(ty + 16) * 33 + tx] = feat[(size_t)(c0 + ty + 16) * NTOT + (n0 + tx)];
            __syncthreads();
            g_featT[(size_t)(n0 + ty) * CIN + (c0 + tx)]      = tile[tx * 33 + ty];
            g_featT[(size_t)(n0 + ty + 16) * CIN + (c0 + tx)] = tile[tx * 33 + ty + 16];
        }
        return;
    }

    // ---------------- FPS path ----------------------------------------------
    float4* spts = (float4*)dyn_smem;                 // [8192] float4 = 128KB
    __shared__ unsigned long long red[2][16];

    const int b = blockIdx.x;
    const float* src = xyz + (size_t)b * NPTS * 3;

    // load 16 consecutive points (48 floats = 12 float4)
    float f[48];
    {
        const float4* s4 = (const float4*)src;
        float4* f4 = (float4*)f;
#pragma unroll
        for (int i = 0; i < 12; i++) f4[i] = s4[t * 12 + i];
    }
    unsigned long long pxp[8], pyp[8], pzp[8];
    float dd[16];
#pragma unroll
    for (int a = 0; a < 8; a++) {
        pxp[a] = f2_pack(f[6 * a + 0], f[6 * a + 3]);
        pyp[a] = f2_pack(f[6 * a + 1], f[6 * a + 4]);
        pzp[a] = f2_pack(f[6 * a + 2], f[6 * a + 5]);
    }
#pragma unroll
    for (int j = 0; j < 16; j++) {
        dd[j] = 1e10f;
        spts[t * 16 + j] = make_float4(f[3 * j + 0], f[3 * j + 1], f[3 * j + 2], 0.0f);
    }
    if (t == 0) {
        g_new_idx[b * NPOINT] = 0;
        g_new_xyz[(size_t)(b * NPOINT) * 3 + 0] = f[0];
        g_new_xyz[(size_t)(b * NPOINT) * 3 + 1] = f[1];
        g_new_xyz[(size_t)(b * NPOINT) * 3 + 2] = f[2];
        out[OFF_IDX + b * NPOINT] = 0.0f;
        out[OFF_XYZ + (size_t)(b * NPOINT) * 3 + 0] = f[0];
        out[OFF_XYZ + (size_t)(b * NPOINT) * 3 + 1] = f[1];
        out[OFF_XYZ + (size_t)(b * NPOINT) * 3 + 2] = f[2];
    }
    __syncthreads();

    // negated last-point coords, packed (x - l == x + (-l), exact)
    const float4 p0 = spts[0];
    unsigned long long nlx = f2_pack(-p0.x, -p0.x);
    unsigned long long nly = f2_pack(-p0.y, -p0.y);
    unsigned long long nlz = f2_pack(-p0.z, -p0.z);

    const int lane = t & 31;
    const int wid = t >> 5;
    const int base = t * 16;

    for (int it = 1; it < NPOINT; ++it) {
        float m = 0.0f;       // dd >= 0 -> u32 bit max == float max
        int mi = 0;
#pragma unroll
        for (int a = 0; a < 8; a++) {
            unsigned long long dx = f2_add(pxp[a], nlx);
            unsigned long long dy = f2_add(pyp[a], nly);
            unsigned long long dz = f2_add(pzp[a], nlz);
            unsigned long long s  = f2_add(f2_add(f2_mul(dx, dx), f2_mul(dy, dy)),
                                           f2_mul(dz, dz));
            float d2l, d2h;
            f2_unpack(s, d2l, d2h);
            const float n0 = fminf(dd[2 * a + 0], d2l);
            const float n1 = fminf(dd[2 * a + 1], d2h);
            dd[2 * a + 0] = n0;
            dd[2 * a + 1] = n1;
            // strict > keeps lowest index on ties (matches jnp.argmax)
            if (n0 > m) { m = n0; mi = 2 * a + 0; }
            if (n1 > m) { m = n1; mi = 2 * a + 1; }
        }
        const unsigned mu = __float_as_uint(m);
        const unsigned wm = redux_max_u32(mu);               // warp max
        const unsigned bal = __ballot_sync(0xffffffffu, mu == wm);
        const int srcl = __ffs(bal) - 1;                     // lowest winning lane
        const int gidx = __shfl_sync(0xffffffffu, base + mi, srcl);
        if (lane == 0)
            red[it & 1][wid] = ((unsigned long long)wm << 32) | (unsigned)gidx;
        __syncthreads();

        // all warps redundantly reduce the 16 warp results
        const unsigned long long pv = red[it & 1][lane & 15];
        const unsigned pval = (unsigned)(pv >> 32);
        const unsigned vm = redux_max_u32(pval);
        const unsigned bal2 = __ballot_sync(0xffffffffu, pval == vm);
        const int wsrc = __ffs(bal2) - 1;                    // lowest winning warp (<16)
        const int idx = __shfl_sync(0xffffffffu, (int)(unsigned)pv, wsrc);

        const float4 w = spts[idx];                          // broadcast LDS.128
        nlx = f2_pack(-w.x, -w.x);
        nly = f2_pack(-w.y, -w.y);
        nlz = f2_pack(-w.z, -w.z);
        if (t == 0) {
            g_new_idx[b * NPOINT + it] = idx;
            g_new_xyz[(size_t)(b * NPOINT + it) * 3 + 0] = w.x;
            g_new_xyz[(size_t)(b * NPOINT + it) * 3 + 1] = w.y;
            g_new_xyz[(size_t)(b * NPOINT + it) * 3 + 2] = w.z;
            out[OFF_IDX + b * NPOINT + it] = (float)idx;
            out[OFF_XYZ + (size_t)(b * NPOINT + it) * 3 + 0] = w.x;
            out[OFF_XYZ + (size_t)(b * NPOINT + it) * 3 + 1] = w.y;
            out[OFF_XYZ + (size_t)(b * NPOINT + it) * 3 + 2] = w.z;
        }
    }
}

// =============================================================================
// 3) Ball query: one warp per center (unchanged; passes exactly).
// =============================================================================
__global__ void __launch_bounds__(256) ballq_kernel(const float* __restrict__ xyz,
                                                    float* __restrict__ out) {
    float* spx = dyn_smem;
    float* spy = spx + NPTS;
    float* spz = spy + NPTS;
    __shared__ int sm_ids[8][NSAMPLE];

    const int b = blockIdx.x >> 6;
    const int cblk = blockIdx.x & 63;
    const float* src = xyz + (size_t)b * NPTS * 3;

    for (int i = threadIdx.x; i < NPTS; i += 256) {
        spx[i] = src[3 * i + 0];
        spy[i] = src[3 * i + 1];
        spz[i] = src[3 * i + 2];
    }
    __syncthreads();

    const int w = threadIdx.x >> 5, lane = threadIdx.x & 31;
    const int gc = b * NPOINT + cblk * 8 + w;
    const float cx = g_new_xyz[(size_t)gc * 3 + 0];
    const float cy = g_new_xyz[(size_t)gc * 3 + 1];
    const float cz = g_new_xyz[(size_t)gc * 3 + 2];

    int count = 0, first = -1;
    for (int chunk = 0; chunk < NPTS / 32; ++chunk) {
        const int p = chunk * 32 + lane;
        float dx = __fsub_rn(cx, spx[p]);
        float dy = __fsub_rn(cy, spy[p]);
        float dz = __fsub_rn(cz, spz[p]);
        float d2 = __fadd_rn(__fadd_rn(__fmul_rn(dx, dx), __fmul_rn(dy, dy)),
                             __fmul_rn(dz, dz));
        const bool in = d2 < R2;
        const unsigned m = __ballot_sync(0xffffffffu, in);
        if (m) {
            if (first < 0) first = chunk * 32 + __ffs(m) - 1;
            if (in) {
                int rank = count + __popc(m & ((1u << lane) - 1u));
                if (rank < NSAMPLE) sm_ids[w][rank] = p;
            }
            count += __popc(m);
            if (count >= NSAMPLE) break;
        }
    }
    __syncwarp();
    if (first < 0) first = 0;
    const int id = (lane < count) ? sm_ids[w][lane] : first;
    g_sample_ids[(size_t)gc * NSAMPLE + lane] = id;
    out[OFF_SIDS + (size_t)gc * NSAMPLE + lane] = (float)id;
}

// =============================================================================
// 4) Fused gather + MLP(67->64->64->128, ReLU each) + max over samples.
//    256 threads, 8x8 register tile, conflict-free column split (c0/c1).
//    Measured at ~87% of the FFMA-3reg roofline.
// =============================================================================
__device__ __forceinline__ void fma_tile(float acc[8][8],
                                         const float4& a0, const float4& a1,
                                         const float4& b0, const float4& b1) {
    const float a[8]  = {a0.x, a0.y, a0.z, a0.w, a1.x, a1.y, a1.z, a1.w};
    const float bb[8] = {b0.x, b0.y, b0.z, b0.w, b1.x, b1.y, b1.z, b1.w};
#pragma unroll
    for (int i = 0; i < 8; i++)
#pragma unroll
        for (int j = 0; j < 8; j++) acc[i][j] += a[i] * bb[j];
}

// acc[i][0..3] -> cols c0..c0+3 ; acc[i][4..7] -> cols c1..c1+3
template <int K, int LDA>
__device__ __forceinline__ void gemm8x8(const float* __restrict__ A,
                                        const float* __restrict__ Bm,
                                        int o0, int c0, int c1, float acc[8][8]) {
#pragma unroll
    for (int i = 0; i < 8; i++)
#pragma unroll
        for (int j = 0; j < 8; j++) acc[i][j] = 0.0f;

    float4 a0 = *(const float4*)&A[o0];
    float4 a1 = *(const float4*)&A[o0 + 4];
    float4 b0 = *(const float4*)&Bm[c0];
    float4 b1 = *(const float4*)&Bm[c1];
#pragma unroll 4
    for (int k = 0; k < K - 1; k++) {
        float4 na0 = *(const float4*)&A[(k + 1) * LDA + o0];
        float4 na1 = *(const float4*)&A[(k + 1) * LDA + o0 + 4];
        float4 nb0 = *(const float4*)&Bm[(k + 1) * 256 + c0];
        float4 nb1 = *(const float4*)&Bm[(k + 1) * 256 + c1];
        fma_tile(acc, a0, a1, b0, b1);
        a0 = na0; a1 = na1; b0 = nb0; b1 = nb1;
    }
    fma_tile(acc, a0, a1, b0, b1);
}

__global__ void __launch_bounds__(256) mlp_kernel(const float* __restrict__ xyz,
                                                  const float* __restrict__ W0,
                                                  const float* __restrict__ b0,
                                                  const float* __restrict__ W1,
                                                  const float* __restrict__ b1,
                                                  const float* __restrict__ W2,
                                                  const float* __restrict__ b2,
                                                  float* __restrict__ out) {
    float* sW0 = dyn_smem;          // [67][64]  (k-major)
    float* sb0 = sW0 + 67 * 64;
    float* sW1 = sb0 + 64;          // [64][64]
    float* sb1 = sW1 + 64 * 64;
    float* sW2 = sb1 + 64;          // [64][128]
    float* sb2 = sW2 + 64 * 128;
    float* X0  = sb2 + 128;         // [67][256]  (also reused as H2 [64][256])
    float* H1  = X0 + 67 * 256;     // [64][256]

    const int tid = threadIdx.x;
    const int b = blockIdx.x >> 6;
    const int cgrp = blockIdx.x & 63;

    // stage weights (transposed to k-major) + biases
    for (int i = tid; i < 67 * 64; i += 256) { int k = i >> 6, o = i & 63;  sW0[i] = W0[o * 67 + k]; }
    for (int i = tid; i < 64 * 64; i += 256) { int k = i >> 6, o = i & 63;  sW1[i] = W1[o * 64 + k]; }
    for (int i = tid; i < 64 * 128; i += 256){ int k = i >> 7, o = i & 127; sW2[i] = W2[o * 64 + k]; }
    if (tid < 64)  { sb0[tid] = b0[tid]; sb1[tid] = b1[tid]; }
    if (tid < 128) { sb2[tid] = b2[tid]; }

    // gather: each thread owns one sample column
    {
        const int s = tid;
        const int cl = s >> 5;
        const int gc = b * NPOINT + cgrp * 8 + cl;
        const int pid = g_sample_ids[(size_t)gc * NSAMPLE + (s & 31)];
        const float* p = xyz + ((size_t)b * NPTS + pid) * 3;
        const float cx = g_new_xyz[(size_t)gc * 3 + 0];
        const float cy = g_new_xyz[(size_t)gc * 3 + 1];
        const float cz = g_new_xyz[(size_t)gc * 3 + 2];
        X0[0 * 256 + s] = p[0] - cx;
        X0[1 * 256 + s] = p[1] - cy;
        X0[2 * 256 + s] = p[2] - cz;
        const float4* fp = (const float4*)(g_featT + ((size_t)b * NPTS + pid) * CIN);
#pragma unroll
        for (int q = 0; q < 16; q++) {
            float4 v = fp[q];
            X0[(3 + 4 * q + 0) * 256 + s] = v.x;
            X0[(3 + 4 * q + 1) * 256 + s] = v.y;
            X0[(3 + 4 * q + 2) * 256 + s] = v.z;
            X0[(3 + 4 * q + 3) * 256 + s] = v.w;
        }
    }
    __syncthreads();

    const int ot = tid >> 5, st = tid & 31;
    const int o0 = ot * 8;
    const int c0 = st * 4, c1 = 128 + st * 4;
    float acc[8][8];

    // layer 1: 67 -> 64
    gemm8x8<67, 64>(sW0, X0, o0, c0, c1, acc);
#pragma unroll
    for (int i = 0; i < 8; i++) {
        const float bi = sb0[o0 + i];
        float4 r0 = make_float4(fmaxf(acc[i][0] + bi, 0.0f), fmaxf(acc[i][1] + bi, 0.0f),
                                fmaxf(acc[i][2] + bi, 0.0f), fmaxf(acc[i][3] + bi, 0.0f));
        float4 r1 = make_float4(fmaxf(acc[i][4] + bi, 0.0f), fmaxf(acc[i][5] + bi, 0.0f),
                                fmaxf(acc[i][6] + bi, 0.0f), fmaxf(acc[i][7] + bi, 0.0f));
        *(float4*)&H1[(o0 + i) * 256 + c0] = r0;
        *(float4*)&H1[(o0 + i) * 256 + c1] = r1;
    }
    __syncthreads();

    // layer 2: 64 -> 64  (write H2 into X0 buffer)
    gemm8x8<64, 64>(sW1, H1, o0, c0, c1, acc);
#pragma unroll
    for (int i = 0; i < 8; i++) {
        const float bi = sb1[o0 + i];
        float4 r0 = make_float4(fmaxf(acc[i][0] + bi, 0.0f), fmaxf(acc[i][1] + bi, 0.0f),
                                fmaxf(acc[i][2] + bi, 0.0f), fmaxf(acc[i][3] + bi, 0.0f));
        float4 r1 = make_float4(fmaxf(acc[i][4] + bi, 0.0f), fmaxf(acc[i][5] + bi, 0.0f),
                                fmaxf(acc[i][6] + bi, 0.0f), fmaxf(acc[i][7] + bi, 0.0f));
        *(float4*)&X0[(o0 + i) * 256 + c0] = r0;
        *(float4*)&X0[(o0 + i) * 256 + c1] = r1;
    }
    __syncthreads();

    // layer 3: 64 -> 128 in two halves, max-over-samples fused in epilogue.
    const int g = st >> 3;
#pragma unroll
    for (int half = 0; half < 2; ++half) {
        gemm8x8<64, 128>(sW2 + half * 64, X0, o0, c0, c1, acc);
#pragma unroll
        for (int i = 0; i < 8; i++) {
            const float bi = sb2[half * 64 + o0 + i];
            float m0 = 0.0f, m1 = 0.0f;   // ReLU outputs are >= 0
#pragma unroll
            for (int j = 0; j < 4; j++) {
                m0 = fmaxf(m0, fmaxf(acc[i][j] + bi, 0.0f));
                m1 = fmaxf(m1, fmaxf(acc[i][4 + j] + bi, 0.0f));
            }
            m0 = fmaxf(m0, __shfl_xor_sync(0xffffffffu, m0, 1));
            m1 = fmaxf(m1, __shfl_xor_sync(0xffffffffu, m1, 1));
            m0 = fmaxf(m0, __shfl_xor_sync(0xffffffffu, m0, 2));
            m1 = fmaxf(m1, __shfl_xor_sync(0xffffffffu, m1, 2));
            m0 = fmaxf(m0, __shfl_xor_sync(0xffffffffu, m0, 4));
            m1 = fmaxf(m1, __shfl_xor_sync(0xffffffffu, m1, 4));
            if ((st & 7) == 0) {
                const int o = half * 64 + o0 + i;
                out[OFF_FEAT + ((size_t)b * 128 + o) * NPOINT + cgrp * 8 + g]     = m0;
                out[OFF_FEAT + ((size_t)b * 128 + o) * NPOINT + cgrp * 8 + 4 + g] = m1;
            }
        }
    }
}

// =============================================================================
extern "C" void kernel_launch(void* const* d_in, const int* in_sizes, int n_in,
                              void* d_out, int out_size) {
    const float* xyz  = (const float*)d_in[0];
    const float* feat = (const float*)d_in[1];
    const float* W0   = (const float*)d_in[3];
    const float* b0   = (const float*)d_in[4];
    const float* W1   = (const float*)d_in[5];
    const float* b1   = (const float*)d_in[6];
    const float* W2   = (const float*)d_in[7];
    const float* b2   = (const float*)d_in[8];
    float* out = (float*)d_out;

    const int smem_fps = NPTS * 4 * sizeof(float);                 // 131072
    const int smem_pts = 3 * NPTS * sizeof(float);                 // 98304
    const int smem_mlp = (67*64 + 64 + 64*64 + 64 + 64*128 + 128
                          + 67*256 + 64*256) * sizeof(float);      // 201472

    cudaFuncSetAttribute(fps_tr_kernel, cudaFuncAttributeMaxDynamicSharedMemorySize, smem_fps);
    cudaFuncSetAttribute(ballq_kernel,  cudaFuncAttributeMaxDynamicSharedMemorySize, smem_pts);
    cudaFuncSetAttribute(mlp_kernel,    cudaFuncAttributeMaxDynamicSharedMemorySize, smem_mlp);

    fps_tr_kernel<<<BATCH + 256, 512, smem_fps>>>(xyz, feat, out);
    ballq_kernel<<<BATCH * (NPOINT / 8), 256, smem_pts>>>(xyz, out);
    mlp_kernel<<<BATCH * (NPOINT / 8), 256, smem_mlp>>>(xyz, W0, b0, W1, b1, W2, b2, out);
}

// round 11
// speedup vs baseline: 1.6393x; 1.2013x over previous
#include <cuda_runtime.h>
#include <cstdint>

// ---------------- problem constants (fixed by this input set) ----------------
#define BATCH    8
#define NPTS     8192
#define NTOT     65536
#define NPOINT   512
#define NSAMPLE  32
#define CIN      64
#define R2       (0.1f * 0.1f)

// d_out packing (float32), tuple flattened in return order:
#define OFF_XYZ   0                                   // new_xyz  [8,512,3]
#define OFF_IDX   (BATCH * NPOINT * 3)                // new_idx  [8,512]
#define OFF_FEAT  (OFF_IDX + BATCH * NPOINT)          // new_feat [8,128,512]
#define OFF_SIDS  (OFF_FEAT + BATCH * 128 * NPOINT)   // sample_ids [8,512,32]

// ---------------- scratch (device globals; no runtime allocation) ------------
__device__ float        g_new_xyz[BATCH * NPOINT * 3];
__device__ float        g_featT[(size_t)NTOT * CIN];  // [n][c] transposed features
__device__ volatile int g_progress[BATCH];            // centers completed per batch
__device__ int          g_tr_done;                    // finished transpose blocks

// ---------------- packed f32x2 helpers (bit-exact per-lane fp32) -------------
__device__ __forceinline__ unsigned long long f2_add(unsigned long long a, unsigned long long b) {
    unsigned long long r;
    asm("add.rn.f32x2 %0, %1, %2;" : "=l"(r) : "l"(a), "l"(b));
    return r;
}
__device__ __forceinline__ unsigned long long f2_mul(unsigned long long a, unsigned long long b) {
    unsigned long long r;
    asm("mul.rn.f32x2 %0, %1, %2;" : "=l"(r) : "l"(a), "l"(b));
    return r;
}
__device__ __forceinline__ unsigned long long f2_pack(float lo, float hi) {
    unsigned long long r;
    asm("mov.b64 %0, {%1, %2};" : "=l"(r) : "f"(lo), "f"(hi));
    return r;
}
__device__ __forceinline__ void f2_unpack(unsigned long long v, float& lo, float& hi) {
    asm("mov.b64 {%0, %1}, %2;" : "=f"(lo), "=f"(hi) : "l"(v));
}
__device__ __forceinline__ unsigned redux_max_u32(unsigned v) {
    unsigned r;
    asm("redux.sync.max.u32 %0, %1, 0xffffffff;" : "=r"(r) : "r"(v));
    return r;
}

extern __shared__ float dyn_smem[];

// ---------------- MLP gemm helpers (256 active threads, 8x8 tiles) -----------
__device__ __forceinline__ void fma_tile(float acc[8][8],
                                         const float4& a0, const float4& a1,
                                         const float4& b0, const float4& b1) {
    const float a[8]  = {a0.x, a0.y, a0.z, a0.w, a1.x, a1.y, a1.z, a1.w};
    const float bb[8] = {b0.x, b0.y, b0.z, b0.w, b1.x, b1.y, b1.z, b1.w};
#pragma unroll
    for (int i = 0; i < 8; i++)
#pragma unroll
        for (int j = 0; j < 8; j++) acc[i][j] += a[i] * bb[j];
}

// acc[i][0..3] -> cols c0..c0+3 ; acc[i][4..7] -> cols c1..c1+3
template <int K, int LDA>
__device__ __forceinline__ void gemm8x8(const float* __restrict__ A,
                                        const float* __restrict__ Bm,
                                        int o0, int c0, int c1, float acc[8][8]) {
#pragma unroll
    for (int i = 0; i < 8; i++)
#pragma unroll
        for (int j = 0; j < 8; j++) acc[i][j] = 0.0f;

    float4 a0 = *(const float4*)&A[o0];
    float4 a1 = *(const float4*)&A[o0 + 4];
    float4 b0 = *(const float4*)&Bm[c0];
    float4 b1 = *(const float4*)&Bm[c1];
#pragma unroll 4
    for (int k = 0; k < K - 1; k++) {
        float4 na0 = *(const float4*)&A[(k + 1) * LDA + o0];
        float4 na1 = *(const float4*)&A[(k + 1) * LDA + o0 + 4];
        float4 nb0 = *(const float4*)&Bm[(k + 1) * 256 + c0];
        float4 nb1 = *(const float4*)&Bm[(k + 1) * 256 + c1];
        fma_tile(acc, a0, a1, b0, b1);
        a0 = na0; a1 = na1; b0 = nb0; b1 = nb1;
    }
    fma_tile(acc, a0, a1, b0, b1);
}

// =============================================================================
// Reset kernel: zero the cross-block handshake counters (graph replays reuse
// device globals, so this must run before the mega kernel each replay).
// =============================================================================
__global__ void reset_kernel() {
    if (threadIdx.x < BATCH) g_progress[threadIdx.x] = 0;
    if (threadIdx.x == 0) g_tr_done = 0;
}

// =============================================================================
// Mega kernel, 776 blocks x 512 threads:
//   blocks 0..7     : FPS (one batch each) + progress publication every 8 iters
//   blocks 8..263   : feature transpose + completion counter
//   blocks 264..775 : fused ballq + gather + MLP for one 8-center group,
//                     spin-waiting on FPS progress (pipelined under FPS).
// =============================================================================
__global__ void __launch_bounds__(512) mega_kernel(const float* __restrict__ xyz,
                                                   const float* __restrict__ feat,
                                                   const float* __restrict__ W0,
                                                   const float* __restrict__ b0v,
                                                   const float* __restrict__ W1,
                                                   const float* __restrict__ b1v,
                                                   const float* __restrict__ W2,
                                                   const float* __restrict__ b2v,
                                                   float* __restrict__ out) {
    const int t = threadIdx.x;
    const int bid = blockIdx.x;

    __shared__ unsigned long long red[2][16];
    __shared__ int sm_ids_sh[8][NSAMPLE];

    // ------------------------------------------------------------------ FPS
    if (bid < BATCH) {
        float4* spts = (float4*)dyn_smem;             // [8192] float4 = 128KB
        const int b = bid;
        const float* src = xyz + (size_t)b * NPTS * 3;

        float f[48];
        {
            const float4* s4 = (const float4*)src;
            float4* f4 = (float4*)f;
#pragma unroll
            for (int i = 0; i < 12; i++) f4[i] = s4[t * 12 + i];
        }
        unsigned long long pxp[8], pyp[8], pzp[8];
        float dd[16];
#pragma unroll
        for (int a = 0; a < 8; a++) {
            pxp[a] = f2_pack(f[6 * a + 0], f[6 * a + 3]);
            pyp[a] = f2_pack(f[6 * a + 1], f[6 * a + 4]);
            pzp[a] = f2_pack(f[6 * a + 2], f[6 * a + 5]);
        }
#pragma unroll
        for (int j = 0; j < 16; j++) {
            dd[j] = 1e10f;
            spts[t * 16 + j] = make_float4(f[3 * j + 0], f[3 * j + 1], f[3 * j + 2], 0.0f);
        }
        if (t == 0) {
            g_new_xyz[(size_t)(b * NPOINT) * 3 + 0] = f[0];
            g_new_xyz[(size_t)(b * NPOINT) * 3 + 1] = f[1];
            g_new_xyz[(size_t)(b * NPOINT) * 3 + 2] = f[2];
            out[OFF_IDX + b * NPOINT] = 0.0f;
            out[OFF_XYZ + (size_t)(b * NPOINT) * 3 + 0] = f[0];
            out[OFF_XYZ + (size_t)(b * NPOINT) * 3 + 1] = f[1];
            out[OFF_XYZ + (size_t)(b * NPOINT) * 3 + 2] = f[2];
        }
        __syncthreads();

        const float4 p0 = spts[0];
        unsigned long long nlx = f2_pack(-p0.x, -p0.x);
        unsigned long long nly = f2_pack(-p0.y, -p0.y);
        unsigned long long nlz = f2_pack(-p0.z, -p0.z);

        const int lane = t & 31;
        const int wid = t >> 5;
        const int base = t * 16;

        for (int it = 1; it < NPOINT; ++it) {
            float m = 0.0f;       // dd >= 0 -> u32 bit max == float max
            int mi = 0;
#pragma unroll
            for (int a = 0; a < 8; a++) {
                unsigned long long dx = f2_add(pxp[a], nlx);
                unsigned long long dy = f2_add(pyp[a], nly);
                unsigned long long dz = f2_add(pzp[a], nlz);
                unsigned long long s  = f2_add(f2_add(f2_mul(dx, dx), f2_mul(dy, dy)),
                                               f2_mul(dz, dz));
                float d2l, d2h;
                f2_unpack(s, d2l, d2h);
                const float n0 = fminf(dd[2 * a + 0], d2l);
                const float n1 = fminf(dd[2 * a + 1], d2h);
                dd[2 * a + 0] = n0;
                dd[2 * a + 1] = n1;
                if (n0 > m) { m = n0; mi = 2 * a + 0; }   // strict > : lowest idx on tie
                if (n1 > m) { m = n1; mi = 2 * a + 1; }
            }
            const unsigned mu = __float_as_uint(m);
            const unsigned wm = redux_max_u32(mu);
            const unsigned bal = __ballot_sync(0xffffffffu, mu == wm);
            const int srcl = __ffs(bal) - 1;
            const int gidx = __shfl_sync(0xffffffffu, base + mi, srcl);
            if (lane == 0)
                red[it & 1][wid] = ((unsigned long long)wm << 32) | (unsigned)gidx;
            __syncthreads();

            const unsigned long long pv = red[it & 1][lane & 15];
            const unsigned pval = (unsigned)(pv >> 32);
            const unsigned vm = redux_max_u32(pval);
            const unsigned bal2 = __ballot_sync(0xffffffffu, pval == vm);
            const int wsrc = __ffs(bal2) - 1;
            const int idx = __shfl_sync(0xffffffffu, (int)(unsigned)pv, wsrc);

            const float4 w = spts[idx];
            nlx = f2_pack(-w.x, -w.x);
            nly = f2_pack(-w.y, -w.y);
            nlz = f2_pack(-w.z, -w.z);
            if (t == 0) {
                g_new_xyz[(size_t)(b * NPOINT + it) * 3 + 0] = w.x;
                g_new_xyz[(size_t)(b * NPOINT + it) * 3 + 1] = w.y;
                g_new_xyz[(size_t)(b * NPOINT + it) * 3 + 2] = w.z;
                out[OFF_IDX + b * NPOINT + it] = (float)idx;
                out[OFF_XYZ + (size_t)(b * NPOINT + it) * 3 + 0] = w.x;
                out[OFF_XYZ + (size_t)(b * NPOINT + it) * 3 + 1] = w.y;
                out[OFF_XYZ + (size_t)(b * NPOINT + it) * 3 + 2] = w.z;
                if ((it & 7) == 7) {           // release-publish every 8 centers
                    __threadfence();
                    g_progress[b] = it + 1;
                }
            }
        }
        return;
    }

    // ------------------------------------------------------------ transpose
    if (bid < BATCH + 256) {
        float* tile = dyn_smem;                       // 32*33 floats
        const int bb = bid - BATCH;                   // 0..255
        const int tx = t & 31, ty = t >> 5;           // ty 0..15
        for (int ti = 0; ti < 16; ++ti) {
            const int tile_id = bb * 16 + ti;         // 0..4095
            const int n0 = (tile_id & 2047) * 32;
            const int c0 = (tile_id >> 11) * 32;
            __syncthreads();
            tile[ty * 33 + tx]        = feat[(size_t)(c0 + ty) * NTOT + (n0 + tx)];
            tile[(ty + 16) * 33 + tx] = feat[(size_t)(c0 + ty + 16) * NTOT + (n0 + tx)];
            __syncthreads();
            g_featT[(size_t)(n0 + ty) * CIN + (c0 + tx)]      = tile[tx * 33 + ty];
            g_featT[(size_t)(n0 + ty + 16) * CIN + (c0 + tx)] = tile[tx * 33 + ty + 16];
        }
        __threadfence();
        __syncthreads();
        if (t == 0) atomicAdd(&g_tr_done, 1);
        return;
    }

    // ------------------------------------------- fused ballq + gather + MLP
    {
        const int m_ = bid - (BATCH + 256);           // 0..511
        const int b = m_ & 7;
        const int cgrp = m_ >> 3;

        float* sW0 = dyn_smem;          // [67][64]  (k-major)
        float* sb0 = sW0 + 67 * 64;
        float* sW1 = sb0 + 64;          // [64][64]
        float* sb1 = sW1 + 64 * 64;
        float* sW2 = sb1 + 64;          // [64][128]
        float* sb2 = sW2 + 64 * 128;
        float* X0  = sb2 + 128;         // [67][256]  (reused as H2)
        float* H1  = X0 + 67 * 256;     // [64][256]
        // during ballq, the X0/H1 region holds staged xyz (3*8192 floats)
        float* spx = X0;
        float* spy = spx + NPTS;
        float* spz = spy + NPTS;

        // stage weights + xyz while FPS may still be running
        for (int i = t; i < 67 * 64; i += 512) { int k = i >> 6, o = i & 63;  sW0[i] = W0[o * 67 + k]; }
        for (int i = t; i < 64 * 64; i += 512) { int k = i >> 6, o = i & 63;  sW1[i] = W1[o * 64 + k]; }
        for (int i = t; i < 64 * 128; i += 512){ int k = i >> 7, o = i & 127; sW2[i] = W2[o * 64 + k]; }
        if (t < 64)  { sb0[t] = b0v[t]; sb1[t] = b1v[t]; }
        else if (t >= 128 && t < 256) { sb2[t - 128] = b2v[t - 128]; }
        {
            const float* src = xyz + (size_t)b * NPTS * 3;
            for (int i = t; i < NPTS; i += 512) {
                spx[i] = src[3 * i + 0];
                spy[i] = src[3 * i + 1];
                spz[i] = src[3 * i + 2];
            }
        }
        __syncthreads();

        // wait for our 8 centers + the transpose
        if (t == 0) {
            const int need = (cgrp + 1) * 8;
            while (g_progress[b] < need) __nanosleep(128);
            while (*(volatile int*)&g_tr_done < 256) __nanosleep(128);
            __threadfence();
        }
        __syncthreads();

        // ---- ball query: warps 0..7, one center each (exact semantics) ----
        const int w = t >> 5, lane = t & 31;
        if (w < 8) {
            const int gc = b * NPOINT + cgrp * 8 + w;
            const float cx = g_new_xyz[(size_t)gc * 3 + 0];
            const float cy = g_new_xyz[(size_t)gc * 3 + 1];
            const float cz = g_new_xyz[(size_t)gc * 3 + 2];

            int count = 0, first = -1;
            for (int chunk = 0; chunk < NPTS / 32; ++chunk) {
                const int p = chunk * 32 + lane;
                float dx = __fsub_rn(cx, spx[p]);
                float dy = __fsub_rn(cy, spy[p]);
                float dz = __fsub_rn(cz, spz[p]);
                float d2 = __fadd_rn(__fadd_rn(__fmul_rn(dx, dx), __fmul_rn(dy, dy)),
                                     __fmul_rn(dz, dz));
                const bool in = d2 < R2;
                const unsigned mm = __ballot_sync(0xffffffffu, in);
                if (mm) {
                    if (first < 0) first = chunk * 32 + __ffs(mm) - 1;
                    if (in) {
                        int rank = count + __popc(mm & ((1u << lane) - 1u));
                        if (rank < NSAMPLE) sm_ids_sh[w][rank] = p;
                    }
                    count += __popc(mm);
                    if (count >= NSAMPLE) break;
                }
            }
            __syncwarp();
            if (first < 0) first = 0;
            const int id = (lane < count) ? sm_ids_sh[w][lane] : first;
            sm_ids_sh[w][lane] = id;
            out[OFF_SIDS + (size_t)gc * NSAMPLE + lane] = (float)id;
        }
        __syncthreads();

        // ---- gather: thread pair (s, s+256) fills one sample column --------
        {
            const int s = t & 255;
            const int half = t >> 8;
            const int cl = s >> 5;
            const int gc = b * NPOINT + cgrp * 8 + cl;
            const int pid = sm_ids_sh[cl][s & 31];
            if (half == 0) {
                const float* p = xyz + ((size_t)b * NPTS + pid) * 3;
                X0[0 * 256 + s] = p[0] - g_new_xyz[(size_t)gc * 3 + 0];
                X0[1 * 256 + s] = p[1] - g_new_xyz[(size_t)gc * 3 + 1];
                X0[2 * 256 + s] = p[2] - g_new_xyz[(size_t)gc * 3 + 2];
            }
            const float4* fp = (const float4*)(g_featT + ((size_t)b * NPTS + pid) * CIN + half * 32);
#pragma unroll
            for (int q = 0; q < 8; q++) {
                float4 v = fp[q];
                const int r = 3 + half * 32 + 4 * q;
                X0[(r + 0) * 256 + s] = v.x;
                X0[(r + 1) * 256 + s] = v.y;
                X0[(r + 2) * 256 + s] = v.z;
                X0[(r + 3) * 256 + s] = v.w;
            }
        }
        __syncthreads();

        // ---- MLP on warps 0..7 (8x8 tiles); warps 8..15 park on barriers ---
        const int ot = t >> 5, st = t & 31;
        const int o0 = ot * 8;
        const int c0 = st * 4, c1 = 128 + st * 4;
        float acc[8][8];

        if (t < 256) {
            gemm8x8<67, 64>(sW0, X0, o0, c0, c1, acc);
#pragma unroll
            for (int i = 0; i < 8; i++) {
                const float bi = sb0[o0 + i];
                float4 r0 = make_float4(fmaxf(acc[i][0] + bi, 0.0f), fmaxf(acc[i][1] + bi, 0.0f),
                                        fmaxf(acc[i][2] + bi, 0.0f), fmaxf(acc[i][3] + bi, 0.0f));
                float4 r1 = make_float4(fmaxf(acc[i][4] + bi, 0.0f), fmaxf(acc[i][5] + bi, 0.0f),
                                        fmaxf(acc[i][6] + bi, 0.0f), fmaxf(acc[i][7] + bi, 0.0f));
                *(float4*)&H1[(o0 + i) * 256 + c0] = r0;
                *(float4*)&H1[(o0 + i) * 256 + c1] = r1;
            }
        }
        __syncthreads();

        if (t < 256) {
            gemm8x8<64, 64>(sW1, H1, o0, c0, c1, acc);
#pragma unroll
            for (int i = 0; i < 8; i++) {
                const float bi = sb1[o0 + i];
                float4 r0 = make_float4(fmaxf(acc[i][0] + bi, 0.0f), fmaxf(acc[i][1] + bi, 0.0f),
                                        fmaxf(acc[i][2] + bi, 0.0f), fmaxf(acc[i][3] + bi, 0.0f));
                float4 r1 = make_float4(fmaxf(acc[i][4] + bi, 0.0f), fmaxf(acc[i][5] + bi, 0.0f),
                                        fmaxf(acc[i][6] + bi, 0.0f), fmaxf(acc[i][7] + bi, 0.0f));
                *(float4*)&X0[(o0 + i) * 256 + c0] = r0;
                *(float4*)&X0[(o0 + i) * 256 + c1] = r1;
            }
        }
        __syncthreads();

        if (t < 256) {
            const int g = st >> 3;
#pragma unroll
            for (int half = 0; half < 2; ++half) {
                gemm8x8<64, 128>(sW2 + half * 64, X0, o0, c0, c1, acc);
#pragma unroll
                for (int i = 0; i < 8; i++) {
                    const float bi = sb2[half * 64 + o0 + i];
                    float m0 = 0.0f, m1 = 0.0f;   // ReLU outputs are >= 0
#pragma unroll
                    for (int j = 0; j < 4; j++) {
                        m0 = fmaxf(m0, fmaxf(acc[i][j] + bi, 0.0f));
                        m1 = fmaxf(m1, fmaxf(acc[i][4 + j] + bi, 0.0f));
                    }
                    m0 = fmaxf(m0, __shfl_xor_sync(0xffffffffu, m0, 1));
                    m1 = fmaxf(m1, __shfl_xor_sync(0xffffffffu, m1, 1));
                    m0 = fmaxf(m0, __shfl_xor_sync(0xffffffffu, m0, 2));
                    m1 = fmaxf(m1, __shfl_xor_sync(0xffffffffu, m1, 2));
                    m0 = fmaxf(m0, __shfl_xor_sync(0xffffffffu, m0, 4));
                    m1 = fmaxf(m1, __shfl_xor_sync(0xffffffffu, m1, 4));
                    if ((st & 7) == 0) {
                        const int o = half * 64 + o0 + i;
                        out[OFF_FEAT + ((size_t)b * 128 + o) * NPOINT + cgrp * 8 + g]     = m0;
                        out[OFF_FEAT + ((size_t)b * 128 + o) * NPOINT + cgrp * 8 + 4 + g] = m1;
                    }
                }
            }
        }
    }
}

// =============================================================================
extern "C" void kernel_launch(void* const* d_in, const int* in_sizes, int n_in,
                              void* d_out, int out_size) {
    const float* xyz  = (const float*)d_in[0];
    const float* feat = (const float*)d_in[1];
    const float* W0   = (const float*)d_in[3];
    const float* b0   = (const float*)d_in[4];
    const float* W1   = (const float*)d_in[5];
    const float* b1   = (const float*)d_in[6];
    const float* W2   = (const float*)d_in[7];
    const float* b2   = (const float*)d_in[8];
    float* out = (float*)d_out;

    const int smem_mega = (67*64 + 64 + 64*64 + 64 + 64*128 + 128
                           + 67*256 + 64*256) * sizeof(float);     // 201472

    cudaFuncSetAttribute(mega_kernel, cudaFuncAttributeMaxDynamicSharedMemorySize, smem_mega);

    reset_kernel<<<1, 32>>>();
    mega_kernel<<<BATCH + 256 + BATCH * (NPOINT / 8), 512, smem_mega>>>(
        xyz, feat, W0, b0, W1, b1, W2, b2, out);
}